// round 12
// baseline (speedup 1.0000x reference)
#include <cuda_runtime.h>
#include <math.h>
#include <stdint.h>

#define BATCH 4
#define SEQ   4096
#define DM    512
#define MROWS (BATCH*SEQ)

__device__ float g_q[MROWS*DM];
__device__ float g_k[MROWS*DM];
__device__ float g_v[MROWS*DM];
__device__ float g_ctx[MROWS*DM];
// packed bf16 hi/lo operands for attention
__device__ __align__(16) uint16_t g_qh[MROWS*DM], g_ql[MROWS*DM];
__device__ __align__(16) uint16_t g_kh[MROWS*DM], g_kl[MROWS*DM];
__device__ __align__(16) uint16_t g_vth[MROWS*DM], g_vtl[MROWS*DM];  // [b][d][s]

__device__ __forceinline__ uint32_t fu(float x) { return __float_as_uint(x); }
// tf32 round (integer ops only — cvt.rna.tf32 is broken on this target)
__device__ __forceinline__ float t32f(float x) {
    uint32_t u = fu(x);
    u = (u + 0x1000u + ((u >> 13) & 1u)) & 0xFFFFE000u;
    return __uint_as_float(u);
}
// bf16 round-to-nearest-even, integer ops; returns fp32 bits of rounded value
__device__ __forceinline__ uint32_t bfr(float x) {
    uint32_t u = fu(x);
    return (u + 0x7FFFu + ((u >> 16) & 1u)) & 0xFFFF0000u;
}
// split (a,b) -> packed bf16 hi pair, packed bf16 lo pair
__device__ __forceinline__ void sp2b(float a, float b, uint32_t& h, uint32_t& l) {
    uint32_t ra = bfr(a), rb = bfr(b);
    h = (ra >> 16) | (rb & 0xFFFF0000u);
    float la = a - __uint_as_float(ra), lb = b - __uint_as_float(rb);
    uint32_t rla = bfr(la), rlb = bfr(lb);
    l = (rla >> 16) | (rlb & 0xFFFF0000u);
}

// tf32 m16n8k8 (VERIFIED R9) — projections
__device__ __forceinline__ void mm8(float* c, const uint32_t* a, uint32_t b0, uint32_t b1) {
    asm volatile("mma.sync.aligned.m16n8k8.row.col.f32.tf32.tf32.f32 "
        "{%0,%1,%2,%3},{%4,%5,%6,%7},{%8,%9},{%0,%1,%2,%3};"
        : "+f"(c[0]), "+f"(c[1]), "+f"(c[2]), "+f"(c[3])
        : "r"(a[0]), "r"(a[1]), "r"(a[2]), "r"(a[3]), "r"(b0), "r"(b1));
}
// bf16 m16n8k16 (VERIFIED R11) — attention
__device__ __forceinline__ void mm16(float* c, const uint32_t* a, uint32_t b0, uint32_t b1) {
    asm volatile("mma.sync.aligned.m16n8k16.row.col.f32.bf16.bf16.f32 "
        "{%0,%1,%2,%3},{%4,%5,%6,%7},{%8,%9},{%0,%1,%2,%3};"
        : "+f"(c[0]), "+f"(c[1]), "+f"(c[2]), "+f"(c[3])
        : "r"(a[0]), "r"(a[1]), "r"(a[2]), "r"(a[3]), "r"(b0), "r"(b1));
}

// ============== tf32 MMA projection GEMM (VERIFIED R9-R11, unchanged) ==============
#define PLDA 36

__device__ __forceinline__ void proj_body(const float* __restrict__ A,
                                          const float* __restrict__ W,
                                          float* __restrict__ C) {
    __shared__ float sA[128 * PLDA];
    __shared__ float sW[64 * PLDA];
    const int t = threadIdx.x, w = t >> 5, lane = t & 31;
    const int g = lane >> 2, q4 = lane & 3;
    const int m0 = blockIdx.y * 128, n0 = blockIdx.x * 64;
    const int wm = (w & 3) * 32, wn = (w >> 2) * 32;

    float acc[2][4][4];
    #pragma unroll
    for (int a = 0; a < 2; a++)
        #pragma unroll
        for (int b = 0; b < 4; b++)
            #pragma unroll
            for (int c = 0; c < 4; c++) acc[a][b][c] = 0.f;

    for (int k0 = 0; k0 < DM; k0 += 32) {
        #pragma unroll
        for (int i = 0; i < 4; i++) {
            int e = t + i * 256, r = e >> 3, j = e & 7;
            float4 v = *(const float4*)&A[(size_t)(m0 + r) * DM + k0 + j * 4];
            float* d = &sA[r * PLDA + j * 4];
            d[0] = t32f(v.x); d[1] = t32f(v.y); d[2] = t32f(v.z); d[3] = t32f(v.w);
        }
        #pragma unroll
        for (int i = 0; i < 2; i++) {
            int e = t + i * 256, r = e >> 3, j = e & 7;
            float4 v = *(const float4*)&W[(size_t)(n0 + r) * DM + k0 + j * 4];
            float* d = &sW[r * PLDA + j * 4];
            d[0] = t32f(v.x); d[1] = t32f(v.y); d[2] = t32f(v.z); d[3] = t32f(v.w);
        }
        __syncthreads();
        #pragma unroll
        for (int kk = 0; kk < 32; kk += 8) {
            uint32_t af[2][4];
            #pragma unroll
            for (int mt = 0; mt < 2; mt++) {
                int base = (wm + mt * 16 + g) * PLDA + kk + q4;
                af[mt][0] = fu(sA[base]);
                af[mt][1] = fu(sA[base + 8 * PLDA]);
                af[mt][2] = fu(sA[base + 4]);
                af[mt][3] = fu(sA[base + 8 * PLDA + 4]);
            }
            #pragma unroll
            for (int nt = 0; nt < 4; nt++) {
                int bb = (wn + nt * 8 + g) * PLDA + kk + q4;
                uint32_t b0 = fu(sW[bb]), b1 = fu(sW[bb + 4]);
                mm8(acc[0][nt], af[0], b0, b1);
                mm8(acc[1][nt], af[1], b0, b1);
            }
        }
        __syncthreads();
    }
    #pragma unroll
    for (int mt = 0; mt < 2; mt++)
        #pragma unroll
        for (int nt = 0; nt < 4; nt++) {
            int r0 = m0 + wm + mt * 16 + g;
            int col = n0 + wn + nt * 8 + 2 * q4;
            float* a = acc[mt][nt];
            C[(size_t)r0 * DM + col]           = a[0];
            C[(size_t)r0 * DM + col + 1]       = a[1];
            C[(size_t)(r0 + 8) * DM + col]     = a[2];
            C[(size_t)(r0 + 8) * DM + col + 1] = a[3];
        }
}

__global__ void __launch_bounds__(256, 1)
qkv_proj(const float* __restrict__ x, const float* __restrict__ Wq,
         const float* __restrict__ Wk, const float* __restrict__ Wv) {
    if (blockIdx.z == 0)      proj_body(x, Wq, g_q);
    else if (blockIdx.z == 1) proj_body(x, Wk, g_k);
    else                      proj_body(x, Wv, g_v);
}

__global__ void __launch_bounds__(256, 1)
out_proj(const float* __restrict__ Wo, float* __restrict__ out) {
    proj_body(g_ctx, Wo, out);
}

// ---------- split Q (scaled) and K into packed bf16 hi/lo ----------
__global__ void __launch_bounds__(256, 1) split_qk() {
    const float scale = 0.04419417382415922f;  // 1/sqrt(512)
    size_t i4 = ((size_t)blockIdx.x * 256 + threadIdx.x) * 4;
    float4 q = *(const float4*)(g_q + i4);
    uint32_t h0, l0, h1, l1;
    sp2b(q.x * scale, q.y * scale, h0, l0);
    sp2b(q.z * scale, q.w * scale, h1, l1);
    *(uint2*)(g_qh + i4) = make_uint2(h0, h1);
    *(uint2*)(g_ql + i4) = make_uint2(l0, l1);
    float4 k = *(const float4*)(g_k + i4);
    sp2b(k.x, k.y, h0, l0);
    sp2b(k.z, k.w, h1, l1);
    *(uint2*)(g_kh + i4) = make_uint2(h0, h1);
    *(uint2*)(g_kl + i4) = make_uint2(l0, l1);
}

// ---------- V transpose + split: g_v[b][s][d] -> g_vth/l[b][d][s] ----------
__global__ void __launch_bounds__(256, 1) vtrans() {
    __shared__ float tile[32][33];
    const int s0 = blockIdx.x * 32, d0 = blockIdx.y * 32, b = blockIdx.z;
    const int tx = threadIdx.x & 31, ty = threadIdx.x >> 5;
    #pragma unroll
    for (int j = 0; j < 4; j++) {
        int rr = ty + j * 8;
        tile[rr][tx] = g_v[((size_t)b * SEQ + s0 + rr) * DM + d0 + tx];
    }
    __syncthreads();
    #pragma unroll
    for (int j = 0; j < 4; j++) {
        int rr = ty + j * 8;
        float v = tile[tx][rr];
        uint32_t rh = bfr(v);
        float lo = v - __uint_as_float(rh);
        size_t o = ((size_t)b * DM + d0 + rr) * SEQ + s0 + tx;
        g_vth[o] = (uint16_t)(rh >> 16);
        g_vtl[o] = (uint16_t)(bfr(lo) >> 16);
    }
}

// ======== split-bf16 MMA flash attention: q-tile 32, k-tile 128, 256 thr ========
// smem trimmed to 104.7KB -> 2 CTAs/SM. Q staged PER CHUNK; scores overlay Q buf.
#define LKW 68           // row stride in words (136 bf16)
#define OQH 0            // Q chunk hi: 32*68 = 2176
#define OQL 2176         // Q chunk lo -> 4352
#define OKH 4352         // K/V chunk hi: 128*68 = 8704
#define OKL 13056        // -> 21760
#define OPH 21760        // P hi: 2176
#define OPL 23936        // P lo -> 26112
#define OA  26112
#define OL  26144
#define A_WORDS 26176
#define A_BYTES (A_WORDS*4)
// fp32 scores [32][132] = 4224 words, overlays Q chunk region (4352 words)

__global__ void __launch_bounds__(256, 2) attn() {
    extern __shared__ uint32_t sh[];
    float* sS = (float*)(sh + OQH);       // overlay: live only between QK and P-split
    float* sAlp = (float*)(sh + OA);
    float* sL = (float*)(sh + OL);
    const int t = threadIdx.x, w = t >> 5, lane = t & 31;
    const int g = lane >> 2, q4 = lane & 3;
    const int qt = 127 - blockIdx.x, b = blockIdx.y;   // longest-first
    const int q0 = qt * 32;
    const int mq = (w & 1) * 16;      // warp's 16 q-rows
    const int wn = (w >> 1) * 32;     // warp's 32-col group
    const int row = t >> 3, sub = t & 7;
    const int ktmax = (q0 + 31) >> 7;

    const uint4* Qh4 = (const uint4*)(g_qh + ((size_t)b * SEQ + q0) * DM);
    const uint4* Ql4 = (const uint4*)(g_ql + ((size_t)b * SEQ + q0) * DM);

    float oacc[4][4][4];
    #pragma unroll
    for (int c = 0; c < 4; c++)
        #pragma unroll
        for (int nt = 0; nt < 4; nt++)
            #pragma unroll
            for (int i = 0; i < 4; i++) oacc[c][nt][i] = 0.f;
    float m_run = -INFINITY, l_run = 0.f;

    for (int kt = 0; kt <= ktmax; kt++) {
        const int k0 = kt * 128;
        float sacc[4][4];
        #pragma unroll
        for (int nt = 0; nt < 4; nt++)
            #pragma unroll
            for (int i = 0; i < 4; i++) sacc[nt][i] = 0.f;

        // ---- S = Q K^T over 4 d-chunks (Q chunk + K chunk staged together) ----
        for (int c = 0; c < 4; c++) {
            const uint4* Kh4 = (const uint4*)(g_kh + ((size_t)b * SEQ + k0) * DM + c * 128);
            const uint4* Kl4 = (const uint4*)(g_kl + ((size_t)b * SEQ + k0) * DM + c * 128);
            #pragma unroll
            for (int i = 0; i < 2; i++) {        // Q chunk 32x128 hi/lo
                int e = t + i * 256, r = e >> 4, j = e & 15;
                *(uint4*)(sh + OQH + r * LKW + j * 4) = Qh4[r * 64 + c * 16 + j];
                *(uint4*)(sh + OQL + r * LKW + j * 4) = Ql4[r * 64 + c * 16 + j];
            }
            #pragma unroll
            for (int i = 0; i < 8; i++) {        // K chunk 128x128 hi/lo
                int e = t + i * 256, r = e >> 4, j = e & 15;
                *(uint4*)(sh + OKH + r * LKW + j * 4) = Kh4[r * 64 + j];
                *(uint4*)(sh + OKL + r * LKW + j * 4) = Kl4[r * 64 + j];
            }
            __syncthreads();
            #pragma unroll
            for (int kk = 0; kk < 128; kk += 16) {
                int ab = (mq + g) * LKW + (kk >> 1) + q4;
                uint32_t ah[4] = { sh[OQH + ab], sh[OQH + ab + 8 * LKW],
                                   sh[OQH + ab + 4], sh[OQH + ab + 8 * LKW + 4] };
                uint32_t al[4] = { sh[OQL + ab], sh[OQL + ab + 8 * LKW],
                                   sh[OQL + ab + 4], sh[OQL + ab + 8 * LKW + 4] };
                #pragma unroll
                for (int nt = 0; nt < 4; nt++) {
                    int bb = (wn + nt * 8 + g) * LKW + (kk >> 1) + q4;
                    uint32_t bh0 = sh[OKH + bb], bh1 = sh[OKH + bb + 4];
                    uint32_t bl0 = sh[OKL + bb], bl1 = sh[OKL + bb + 4];
                    mm16(sacc[nt], ah, bh0, bh1);
                    mm16(sacc[nt], ah, bl0, bl1);
                    mm16(sacc[nt], al, bh0, bh1);
                }
            }
            __syncthreads();
        }
        // ---- S -> smem (overlays Q chunk buffer; Q phase is done) ----
        #pragma unroll
        for (int nt = 0; nt < 4; nt++) {
            int r0 = mq + g, col = wn + nt * 8 + 2 * q4;
            sS[r0 * 132 + col]           = sacc[nt][0];
            sS[r0 * 132 + col + 1]       = sacc[nt][1];
            sS[(r0 + 8) * 132 + col]     = sacc[nt][2];
            sS[(r0 + 8) * 132 + col + 1] = sacc[nt][3];
        }
        __syncthreads();
        // ---- online softmax: 8 threads/row, 16 keys each ----
        float sv[16], mx = -INFINITY;
        const bool lastt = (kt == ktmax);
        #pragma unroll
        for (int i = 0; i < 16; i++) {
            float s = sS[row * 132 + sub * 16 + i];
            if (lastt && (k0 + sub * 16 + i > q0 + row)) s = -INFINITY;
            sv[i] = s;
            mx = fmaxf(mx, s);
        }
        #pragma unroll
        for (int o = 1; o < 8; o <<= 1) mx = fmaxf(mx, __shfl_xor_sync(~0u, mx, o));
        float mnew = fmaxf(m_run, mx);
        float alpha = __expf(m_run - mnew);
        float ps = 0.f;
        #pragma unroll
        for (int i = 0; i < 16; i++) { sv[i] = __expf(sv[i] - mnew); ps += sv[i]; }
        #pragma unroll
        for (int o = 1; o < 8; o <<= 1) ps += __shfl_xor_sync(~0u, ps, o);
        l_run = l_run * alpha + ps;
        m_run = mnew;
        if (sub == 0) sAlp[row] = alpha;
        #pragma unroll
        for (int i = 0; i < 16; i += 2) {                 // P -> packed bf16 hi/lo
            uint32_t h, l;
            sp2b(sv[i], sv[i + 1], h, l);
            sh[OPH + row * LKW + sub * 8 + (i >> 1)] = h;
            sh[OPL + row * LKW + sub * 8 + (i >> 1)] = l;
        }
        __syncthreads();
        // ---- rescale O ----
        {
            float a0 = sAlp[mq + g], a1 = sAlp[mq + g + 8];
            #pragma unroll
            for (int c = 0; c < 4; c++)
                #pragma unroll
                for (int nt = 0; nt < 4; nt++) {
                    oacc[c][nt][0] *= a0; oacc[c][nt][1] *= a0;
                    oacc[c][nt][2] *= a1; oacc[c][nt][3] *= a1;
                }
        }
        // ---- O += P V over 4 d-chunks (V^T tiles reuse K buffers) ----
        for (int c = 0; c < 4; c++) {
            const uint4* Vh4 = (const uint4*)(g_vth + ((size_t)b * DM + c * 128) * SEQ + k0);
            const uint4* Vl4 = (const uint4*)(g_vtl + ((size_t)b * DM + c * 128) * SEQ + k0);
            #pragma unroll
            for (int i = 0; i < 8; i++) {
                int e = t + i * 256, r = e >> 4, j = e & 15;  // row=d-local, 16 uint4/row
                *(uint4*)(sh + OKH + r * LKW + j * 4) = Vh4[r * 512 + j];
                *(uint4*)(sh + OKL + r * LKW + j * 4) = Vl4[r * 512 + j];
            }
            __syncthreads();
            #pragma unroll
            for (int kk = 0; kk < 128; kk += 16) {
                int ab = (mq + g) * LKW + (kk >> 1) + q4;
                uint32_t ph[4] = { sh[OPH + ab], sh[OPH + ab + 8 * LKW],
                                   sh[OPH + ab + 4], sh[OPH + ab + 8 * LKW + 4] };
                uint32_t pl[4] = { sh[OPL + ab], sh[OPL + ab + 8 * LKW],
                                   sh[OPL + ab + 4], sh[OPL + ab + 8 * LKW + 4] };
                #pragma unroll
                for (int nt = 0; nt < 4; nt++) {
                    int bb = (wn + nt * 8 + g) * LKW + (kk >> 1) + q4;   // row = d
                    uint32_t vh0 = sh[OKH + bb], vh1 = sh[OKH + bb + 4];
                    uint32_t vl0 = sh[OKL + bb], vl1 = sh[OKL + bb + 4];
                    mm16(oacc[c][nt], ph, vh0, vh1);
                    mm16(oacc[c][nt], ph, vl0, vl1);
                    mm16(oacc[c][nt], pl, vh0, vh1);
                }
            }
            __syncthreads();
        }
    }
    // ---- epilogue ----
    if (sub == 0) sL[row] = l_run;
    __syncthreads();
    {
        float li0 = 1.f / sL[mq + g], li1 = 1.f / sL[mq + g + 8];
        #pragma unroll
        for (int c = 0; c < 4; c++)
            #pragma unroll
            for (int nt = 0; nt < 4; nt++) {
                int col = c * 128 + wn + nt * 8 + 2 * q4;
                size_t r0 = ((size_t)b * SEQ + q0 + mq + g) * DM;
                float* a = oacc[c][nt];
                g_ctx[r0 + col]              = a[0] * li0;
                g_ctx[r0 + col + 1]          = a[1] * li0;
                g_ctx[r0 + 8 * DM + col]     = a[2] * li1;
                g_ctx[r0 + 8 * DM + col + 1] = a[3] * li1;
            }
    }
}

extern "C" void kernel_launch(void* const* d_in, const int* in_sizes, int n_in,
                              void* d_out, int out_size) {
    (void)in_sizes; (void)n_in; (void)out_size;
    const float* x  = (const float*)d_in[0];
    const float* Wq = (const float*)d_in[1];
    const float* Wk = (const float*)d_in[2];
    const float* Wv = (const float*)d_in[3];
    const float* Wo = (const float*)d_in[4];
    float* out = (float*)d_out;

    qkv_proj<<<dim3(8, 128, 3), 256>>>(x, Wq, Wk, Wv);
    split_qk<<<MROWS * DM / 4 / 256, 256>>>();
    vtrans<<<dim3(SEQ / 32, DM / 32, BATCH), 256>>>();

    cudaFuncSetAttribute(attn, cudaFuncAttributeMaxDynamicSharedMemorySize, A_BYTES);
    attn<<<dim3(128, BATCH), 256, A_BYTES>>>();

    out_proj<<<dim3(8, 128), 256>>>(Wo, out);
}

// round 13
// speedup vs baseline: 1.4191x; 1.4191x over previous
#include <cuda_runtime.h>
#include <math.h>
#include <stdint.h>

#define BATCH 4
#define SEQ   4096
#define DM    512
#define MROWS (BATCH*SEQ)

__device__ float g_q[MROWS*DM];
__device__ float g_k[MROWS*DM];
__device__ float g_v[MROWS*DM];
__device__ float g_ctx[MROWS*DM];
// packed bf16 hi/lo operands for attention
__device__ __align__(16) uint16_t g_qh[MROWS*DM], g_ql[MROWS*DM];
__device__ __align__(16) uint16_t g_kh[MROWS*DM], g_kl[MROWS*DM];
__device__ __align__(16) uint16_t g_vth[MROWS*DM], g_vtl[MROWS*DM];  // [b][d][s]

__device__ __forceinline__ uint32_t fu(float x) { return __float_as_uint(x); }
// tf32 round (integer ops only — cvt.rna.tf32 is broken on this target)
__device__ __forceinline__ float t32f(float x) {
    uint32_t u = fu(x);
    u = (u + 0x1000u + ((u >> 13) & 1u)) & 0xFFFFE000u;
    return __uint_as_float(u);
}
// bf16 round-to-nearest-even (integer ops); returns fp32 bits of rounded value
__device__ __forceinline__ uint32_t bfr(float x) {
    uint32_t u = fu(x);
    return (u + 0x7FFFu + ((u >> 16) & 1u)) & 0xFFFF0000u;
}
__device__ __forceinline__ void sp2b(float a, float b, uint32_t& h, uint32_t& l) {
    uint32_t ra = bfr(a), rb = bfr(b);
    h = (ra >> 16) | (rb & 0xFFFF0000u);
    float la = a - __uint_as_float(ra), lb = b - __uint_as_float(rb);
    uint32_t rla = bfr(la), rlb = bfr(lb);
    l = (rla >> 16) | (rlb & 0xFFFF0000u);
}

// tf32 m16n8k8 (VERIFIED) — projections
__device__ __forceinline__ void mm8(float* c, const uint32_t* a, uint32_t b0, uint32_t b1) {
    asm volatile("mma.sync.aligned.m16n8k8.row.col.f32.tf32.tf32.f32 "
        "{%0,%1,%2,%3},{%4,%5,%6,%7},{%8,%9},{%0,%1,%2,%3};"
        : "+f"(c[0]), "+f"(c[1]), "+f"(c[2]), "+f"(c[3])
        : "r"(a[0]), "r"(a[1]), "r"(a[2]), "r"(a[3]), "r"(b0), "r"(b1));
}
// bf16 m16n8k16 (VERIFIED) — attention
__device__ __forceinline__ void mm16(float* c, const uint32_t* a, uint32_t b0, uint32_t b1) {
    asm volatile("mma.sync.aligned.m16n8k16.row.col.f32.bf16.bf16.f32 "
        "{%0,%1,%2,%3},{%4,%5,%6,%7},{%8,%9},{%0,%1,%2,%3};"
        : "+f"(c[0]), "+f"(c[1]), "+f"(c[2]), "+f"(c[3])
        : "r"(a[0]), "r"(a[1]), "r"(a[2]), "r"(a[3]), "r"(b0), "r"(b1));
}
// cp.async 16B global->shared
__device__ __forceinline__ void cpa16(uint32_t saddr, const void* g) {
    asm volatile("cp.async.cg.shared.global [%0],[%1],16;" :: "r"(saddr), "l"(g));
}
#define CPC()  asm volatile("cp.async.commit_group;" ::: "memory")
#define CPW1() asm volatile("cp.async.wait_group 1;" ::: "memory")
#define CPW0() asm volatile("cp.async.wait_group 0;" ::: "memory")

// ============== tf32 MMA projection GEMM (VERIFIED R9-R12, unchanged) ==============
#define PLDA 36

__device__ __forceinline__ void proj_body(const float* __restrict__ A,
                                          const float* __restrict__ W,
                                          float* __restrict__ C) {
    __shared__ float sA[128 * PLDA];
    __shared__ float sW[64 * PLDA];
    const int t = threadIdx.x, w = t >> 5, lane = t & 31;
    const int g = lane >> 2, q4 = lane & 3;
    const int m0 = blockIdx.y * 128, n0 = blockIdx.x * 64;
    const int wm = (w & 3) * 32, wn = (w >> 2) * 32;

    float acc[2][4][4];
    #pragma unroll
    for (int a = 0; a < 2; a++)
        #pragma unroll
        for (int b = 0; b < 4; b++)
            #pragma unroll
            for (int c = 0; c < 4; c++) acc[a][b][c] = 0.f;

    for (int k0 = 0; k0 < DM; k0 += 32) {
        #pragma unroll
        for (int i = 0; i < 4; i++) {
            int e = t + i * 256, r = e >> 3, j = e & 7;
            float4 v = *(const float4*)&A[(size_t)(m0 + r) * DM + k0 + j * 4];
            float* d = &sA[r * PLDA + j * 4];
            d[0] = t32f(v.x); d[1] = t32f(v.y); d[2] = t32f(v.z); d[3] = t32f(v.w);
        }
        #pragma unroll
        for (int i = 0; i < 2; i++) {
            int e = t + i * 256, r = e >> 3, j = e & 7;
            float4 v = *(const float4*)&W[(size_t)(n0 + r) * DM + k0 + j * 4];
            float* d = &sW[r * PLDA + j * 4];
            d[0] = t32f(v.x); d[1] = t32f(v.y); d[2] = t32f(v.z); d[3] = t32f(v.w);
        }
        __syncthreads();
        #pragma unroll
        for (int kk = 0; kk < 32; kk += 8) {
            uint32_t af[2][4];
            #pragma unroll
            for (int mt = 0; mt < 2; mt++) {
                int base = (wm + mt * 16 + g) * PLDA + kk + q4;
                af[mt][0] = fu(sA[base]);
                af[mt][1] = fu(sA[base + 8 * PLDA]);
                af[mt][2] = fu(sA[base + 4]);
                af[mt][3] = fu(sA[base + 8 * PLDA + 4]);
            }
            #pragma unroll
            for (int nt = 0; nt < 4; nt++) {
                int bb = (wn + nt * 8 + g) * PLDA + kk + q4;
                uint32_t b0 = fu(sW[bb]), b1 = fu(sW[bb + 4]);
                mm8(acc[0][nt], af[0], b0, b1);
                mm8(acc[1][nt], af[1], b0, b1);
            }
        }
        __syncthreads();
    }
    #pragma unroll
    for (int mt = 0; mt < 2; mt++)
        #pragma unroll
        for (int nt = 0; nt < 4; nt++) {
            int r0 = m0 + wm + mt * 16 + g;
            int col = n0 + wn + nt * 8 + 2 * q4;
            float* a = acc[mt][nt];
            C[(size_t)r0 * DM + col]           = a[0];
            C[(size_t)r0 * DM + col + 1]       = a[1];
            C[(size_t)(r0 + 8) * DM + col]     = a[2];
            C[(size_t)(r0 + 8) * DM + col + 1] = a[3];
        }
}

__global__ void __launch_bounds__(256, 1)
qkv_proj(const float* __restrict__ x, const float* __restrict__ Wq,
         const float* __restrict__ Wk, const float* __restrict__ Wv) {
    if (blockIdx.z == 0)      proj_body(x, Wq, g_q);
    else if (blockIdx.z == 1) proj_body(x, Wk, g_k);
    else                      proj_body(x, Wv, g_v);
}

__global__ void __launch_bounds__(256, 1)
out_proj(const float* __restrict__ Wo, float* __restrict__ out) {
    proj_body(g_ctx, Wo, out);
}

// ---------- split Q (scaled) and K into packed bf16 hi/lo ----------
__global__ void __launch_bounds__(256, 1) split_qk() {
    const float scale = 0.04419417382415922f;  // 1/sqrt(512)
    size_t i4 = ((size_t)blockIdx.x * 256 + threadIdx.x) * 4;
    float4 q = *(const float4*)(g_q + i4);
    uint32_t h0, l0, h1, l1;
    sp2b(q.x * scale, q.y * scale, h0, l0);
    sp2b(q.z * scale, q.w * scale, h1, l1);
    *(uint2*)(g_qh + i4) = make_uint2(h0, h1);
    *(uint2*)(g_ql + i4) = make_uint2(l0, l1);
    float4 k = *(const float4*)(g_k + i4);
    sp2b(k.x, k.y, h0, l0);
    sp2b(k.z, k.w, h1, l1);
    *(uint2*)(g_kh + i4) = make_uint2(h0, h1);
    *(uint2*)(g_kl + i4) = make_uint2(l0, l1);
}

// ---------- V transpose + split: g_v[b][s][d] -> g_vth/l[b][d][s] ----------
__global__ void __launch_bounds__(256, 1) vtrans() {
    __shared__ float tile[32][33];
    const int s0 = blockIdx.x * 32, d0 = blockIdx.y * 32, b = blockIdx.z;
    const int tx = threadIdx.x & 31, ty = threadIdx.x >> 5;
    #pragma unroll
    for (int j = 0; j < 4; j++) {
        int rr = ty + j * 8;
        tile[rr][tx] = g_v[((size_t)b * SEQ + s0 + rr) * DM + d0 + tx];
    }
    __syncthreads();
    #pragma unroll
    for (int j = 0; j < 4; j++) {
        int rr = ty + j * 8;
        float v = tile[tx][rr];
        uint32_t rh = bfr(v);
        float lo = v - __uint_as_float(rh);
        size_t o = ((size_t)b * DM + d0 + rr) * SEQ + s0 + tx;
        g_vth[o] = (uint16_t)(rh >> 16);
        g_vtl[o] = (uint16_t)(bfr(lo) >> 16);
    }
}

// ==== split-bf16 MMA flash attention, cp.async double-buffered, 1 CTA/SM ====
#define LQW 260          // Q row stride in words
#define LKW 68           // K/V/P row stride in words
#define OQH 0            // Q hi 32*260 = 8320
#define OQL 8320         // Q lo -> 16640
#define OB0H 16640       // buffer0 hi 128*68 = 8704
#define OB0L 25344       // buffer0 lo -> 34048
#define OB1H 34048       // buffer1 hi
#define OB1L 42752       // buffer1 lo -> 51456
#define OSP  51456       // fp32 S [32][132]=4224 OVERLAYS P hi/lo (4352)
#define OPH  OSP
#define OPL  (OSP + 2176)
#define OA   55808
#define OL   55840
#define A_WORDS 55872
#define A_BYTES (A_WORDS*4)

// stage one 128x128 bf16 chunk pair (hi+lo) via cp.async (8+8 x 16B per thread)
__device__ __forceinline__ void issue_chunk(uint32_t sb, uint32_t oh, uint32_t ol,
                                            const uint4* GH, const uint4* GL,
                                            int strideU4, int t) {
    #pragma unroll
    for (int i = 0; i < 8; i++) {
        int e = t + i * 256, r = e >> 4, j = e & 15;
        cpa16(sb + (oh + r * LKW + j * 4) * 4, GH + (size_t)r * strideU4 + j);
        cpa16(sb + (ol + r * LKW + j * 4) * 4, GL + (size_t)r * strideU4 + j);
    }
}

__global__ void __launch_bounds__(256, 1) attn() {
    extern __shared__ uint32_t sh[];
    const uint32_t sb = (uint32_t)__cvta_generic_to_shared(sh);
    float* sS = (float*)(sh + OSP);
    float* sAlp = (float*)(sh + OA);
    float* sL = (float*)(sh + OL);
    const int t = threadIdx.x, w = t >> 5, lane = t & 31;
    const int g = lane >> 2, q4 = lane & 3;
    const int qt = 127 - blockIdx.x, b = blockIdx.y;   // longest-first
    const int q0 = qt * 32;
    const int mq = (w & 1) * 16;
    const int wn = (w >> 1) * 32;
    const int row = t >> 3, sub = t & 7;
    const int ktmax = (q0 + 31) >> 7;

    // stage full Q tile (plain loads; first barrier covers it)
    {
        const uint4* Qh4 = (const uint4*)(g_qh + ((size_t)b * SEQ + q0) * DM);
        const uint4* Ql4 = (const uint4*)(g_ql + ((size_t)b * SEQ + q0) * DM);
        #pragma unroll
        for (int i = 0; i < 8; i++) {
            int e = t + i * 256, r = e >> 6, j = e & 63;
            *(uint4*)(sh + OQH + r * LQW + j * 4) = Qh4[r * 64 + j];
            *(uint4*)(sh + OQL + r * LQW + j * 4) = Ql4[r * 64 + j];
        }
    }
    // prefetch K chunk 0 of first k-tile into buf0
    {
        const uint4* KH4 = (const uint4*)(g_kh + ((size_t)b * SEQ) * DM);
        const uint4* KL4 = (const uint4*)(g_kl + ((size_t)b * SEQ) * DM);
        issue_chunk(sb, OB0H, OB0L, KH4, KL4, 64, t);
        CPC();
    }
    float oacc[4][4][4];
    #pragma unroll
    for (int c = 0; c < 4; c++)
        #pragma unroll
        for (int nt = 0; nt < 4; nt++)
            #pragma unroll
            for (int i = 0; i < 4; i++) oacc[c][nt][i] = 0.f;
    float m_run = -INFINITY, l_run = 0.f;

    for (int kt = 0; kt <= ktmax; kt++) {
        const int k0 = kt * 128;
        const uint4* KH4 = (const uint4*)(g_kh + ((size_t)b * SEQ + k0) * DM);
        const uint4* KL4 = (const uint4*)(g_kl + ((size_t)b * SEQ + k0) * DM);
        float sacc[4][4];
        #pragma unroll
        for (int nt = 0; nt < 4; nt++)
            #pragma unroll
            for (int i = 0; i < 4; i++) sacc[nt][i] = 0.f;

        // ---- QK over 4 d-chunks, pipelined ----
        #pragma unroll
        for (int c = 0; c < 4; c++) {
            if (c < 3) {  // prefetch next K chunk into other buffer
                uint32_t oh = ((c + 1) & 1) ? OB1H : OB0H;
                uint32_t ol = ((c + 1) & 1) ? OB1L : OB0L;
                issue_chunk(sb, oh, ol, KH4 + (c + 1) * 16, KL4 + (c + 1) * 16, 64, t);
            } else {      // prefetch V chunk 0 into buf0 (consumed after softmax)
                const uint4* VH4 = (const uint4*)(g_vth + ((size_t)b * DM) * SEQ + k0);
                const uint4* VL4 = (const uint4*)(g_vtl + ((size_t)b * DM) * SEQ + k0);
                issue_chunk(sb, OB0H, OB0L, VH4, VL4, 512, t);
            }
            CPC();
            CPW1();               // current chunk's group complete
            __syncthreads();
            uint32_t okh = (c & 1) ? OB1H : OB0H;
            uint32_t okl = (c & 1) ? OB1L : OB0L;
            #pragma unroll
            for (int kk = 0; kk < 128; kk += 16) {
                int ab = (mq + g) * LQW + ((c * 128 + kk) >> 1) + q4;
                uint32_t ah[4] = { sh[OQH + ab], sh[OQH + ab + 8 * LQW],
                                   sh[OQH + ab + 4], sh[OQH + ab + 8 * LQW + 4] };
                uint32_t al[4] = { sh[OQL + ab], sh[OQL + ab + 8 * LQW],
                                   sh[OQL + ab + 4], sh[OQL + ab + 8 * LQW + 4] };
                #pragma unroll
                for (int nt = 0; nt < 4; nt++) {
                    int bb = (wn + nt * 8 + g) * LKW + (kk >> 1) + q4;
                    uint32_t bh0 = sh[okh + bb], bh1 = sh[okh + bb + 4];
                    uint32_t bl0 = sh[okl + bb], bl1 = sh[okl + bb + 4];
                    mm16(sacc[nt], ah, bh0, bh1);
                    mm16(sacc[nt], ah, bl0, bl1);
                    mm16(sacc[nt], al, bh0, bh1);
                }
            }
            __syncthreads();
        }
        // ---- S -> smem (overlay region; P not yet written) ----
        #pragma unroll
        for (int nt = 0; nt < 4; nt++) {
            int r0 = mq + g, col = wn + nt * 8 + 2 * q4;
            sS[r0 * 132 + col]           = sacc[nt][0];
            sS[r0 * 132 + col + 1]       = sacc[nt][1];
            sS[(r0 + 8) * 132 + col]     = sacc[nt][2];
            sS[(r0 + 8) * 132 + col + 1] = sacc[nt][3];
        }
        __syncthreads();
        // ---- online softmax: 8 threads/row, 16 keys each ----
        float sv[16], mx = -INFINITY;
        const bool lastt = (kt == ktmax);
        #pragma unroll
        for (int i = 0; i < 16; i++) {
            float s = sS[row * 132 + sub * 16 + i];
            if (lastt && (k0 + sub * 16 + i > q0 + row)) s = -INFINITY;
            sv[i] = s;
            mx = fmaxf(mx, s);
        }
        #pragma unroll
        for (int o = 1; o < 8; o <<= 1) mx = fmaxf(mx, __shfl_xor_sync(~0u, mx, o));
        float mnew = fmaxf(m_run, mx);
        float alpha = __expf(m_run - mnew);
        float ps = 0.f;
        #pragma unroll
        for (int i = 0; i < 16; i++) { sv[i] = __expf(sv[i] - mnew); ps += sv[i]; }
        #pragma unroll
        for (int o = 1; o < 8; o <<= 1) ps += __shfl_xor_sync(~0u, ps, o);
        l_run = l_run * alpha + ps;
        m_run = mnew;
        __syncthreads();          // all S reads done before P overlays it
        if (sub == 0) sAlp[row] = alpha;
        #pragma unroll
        for (int i = 0; i < 16; i += 2) {
            uint32_t h, l;
            sp2b(sv[i], sv[i + 1], h, l);
            sh[OPH + row * LKW + sub * 8 + (i >> 1)] = h;
            sh[OPL + row * LKW + sub * 8 + (i >> 1)] = l;
        }
        __syncthreads();
        // ---- rescale O ----
        {
            float a0 = sAlp[mq + g], a1 = sAlp[mq + g + 8];
            #pragma unroll
            for (int c = 0; c < 4; c++)
                #pragma unroll
                for (int nt = 0; nt < 4; nt++) {
                    oacc[c][nt][0] *= a0; oacc[c][nt][1] *= a0;
                    oacc[c][nt][2] *= a1; oacc[c][nt][3] *= a1;
                }
        }
        // ---- PV over 4 d-chunks, pipelined (V0 already in flight) ----
        const int nk0 = (kt < ktmax) ? k0 + 128 : k0;
        #pragma unroll
        for (int c = 0; c < 4; c++) {
            if (c < 3) {
                const uint4* VH4 = (const uint4*)(g_vth + ((size_t)b * DM + (c + 1) * 128) * SEQ + k0);
                const uint4* VL4 = (const uint4*)(g_vtl + ((size_t)b * DM + (c + 1) * 128) * SEQ + k0);
                uint32_t oh = ((c + 1) & 1) ? OB1H : OB0H;
                uint32_t ol = ((c + 1) & 1) ? OB1L : OB0L;
                issue_chunk(sb, oh, ol, VH4, VL4, 512, t);
            } else {      // prefetch next k-tile's K chunk 0 into buf0
                const uint4* NKH4 = (const uint4*)(g_kh + ((size_t)b * SEQ + nk0) * DM);
                const uint4* NKL4 = (const uint4*)(g_kl + ((size_t)b * SEQ + nk0) * DM);
                issue_chunk(sb, OB0H, OB0L, NKH4, NKL4, 64, t);
            }
            CPC();
            CPW1();
            __syncthreads();
            uint32_t ovh = (c & 1) ? OB1H : OB0H;
            uint32_t ovl = (c & 1) ? OB1L : OB0L;
            #pragma unroll
            for (int kk = 0; kk < 128; kk += 16) {
                int ab = (mq + g) * LKW + (kk >> 1) + q4;
                uint32_t ph[4] = { sh[OPH + ab], sh[OPH + ab + 8 * LKW],
                                   sh[OPH + ab + 4], sh[OPH + ab + 8 * LKW + 4] };
                uint32_t pl[4] = { sh[OPL + ab], sh[OPL + ab + 8 * LKW],
                                   sh[OPL + ab + 4], sh[OPL + ab + 8 * LKW + 4] };
                #pragma unroll
                for (int nt = 0; nt < 4; nt++) {
                    int bb = (wn + nt * 8 + g) * LKW + (kk >> 1) + q4;   // row = d
                    uint32_t vh0 = sh[ovh + bb], vh1 = sh[ovh + bb + 4];
                    uint32_t vl0 = sh[ovl + bb], vl1 = sh[ovl + bb + 4];
                    mm16(oacc[c][nt], ph, vh0, vh1);
                    mm16(oacc[c][nt], ph, vl0, vl1);
                    mm16(oacc[c][nt], pl, vh0, vh1);
                }
            }
            __syncthreads();
        }
    }
    // ---- epilogue ----
    CPW0();
    if (sub == 0) sL[row] = l_run;
    __syncthreads();
    {
        float li0 = 1.f / sL[mq + g], li1 = 1.f / sL[mq + g + 8];
        #pragma unroll
        for (int c = 0; c < 4; c++)
            #pragma unroll
            for (int nt = 0; nt < 4; nt++) {
                int col = c * 128 + wn + nt * 8 + 2 * q4;
                size_t r0 = ((size_t)b * SEQ + q0 + mq + g) * DM;
                float* a = oacc[c][nt];
                g_ctx[r0 + col]              = a[0] * li0;
                g_ctx[r0 + col + 1]          = a[1] * li0;
                g_ctx[r0 + 8 * DM + col]     = a[2] * li1;
                g_ctx[r0 + 8 * DM + col + 1] = a[3] * li1;
            }
    }
}

extern "C" void kernel_launch(void* const* d_in, const int* in_sizes, int n_in,
                              void* d_out, int out_size) {
    (void)in_sizes; (void)n_in; (void)out_size;
    const float* x  = (const float*)d_in[0];
    const float* Wq = (const float*)d_in[1];
    const float* Wk = (const float*)d_in[2];
    const float* Wv = (const float*)d_in[3];
    const float* Wo = (const float*)d_in[4];
    float* out = (float*)d_out;

    qkv_proj<<<dim3(8, 128, 3), 256>>>(x, Wq, Wk, Wv);
    split_qk<<<MROWS * DM / 4 / 256, 256>>>();
    vtrans<<<dim3(SEQ / 32, DM / 32, BATCH), 256>>>();

    cudaFuncSetAttribute(attn, cudaFuncAttributeMaxDynamicSharedMemorySize, A_BYTES);
    attn<<<dim3(128, BATCH), 256, A_BYTES>>>();

    out_proj<<<dim3(8, 128), 256>>>(Wo, out);
}

// round 15
// speedup vs baseline: 1.7352x; 1.2227x over previous
#include <cuda_runtime.h>
#include <math.h>
#include <stdint.h>

#define BATCH 4
#define SEQ   4096
#define DM    512
#define MROWS (BATCH*SEQ)

__device__ float g_q[MROWS*DM];
__device__ float g_k[MROWS*DM];
__device__ float g_v[MROWS*DM];
__device__ float g_ctx[MROWS*DM];
// fragment-major packed bf16 hi/lo operands (uint32 words = bf16 pairs)
__device__ __align__(16) uint32_t g_qh[MROWS*DM/2], g_ql[MROWS*DM/2];
__device__ __align__(16) uint32_t g_kh[MROWS*DM/2], g_kl[MROWS*DM/2];
__device__ __align__(16) uint32_t g_vth[MROWS*DM/2], g_vtl[MROWS*DM/2];

__device__ __forceinline__ uint32_t fu(float x) { return __float_as_uint(x); }
// tf32 round (integer ops only — cvt.rna.tf32 is broken on this target)
__device__ __forceinline__ float t32f(float x) {
    uint32_t u = fu(x);
    u = (u + 0x1000u + ((u >> 13) & 1u)) & 0xFFFFE000u;
    return __uint_as_float(u);
}
// bf16 round-to-nearest-even (integer ops)
__device__ __forceinline__ uint32_t bfr(float x) {
    uint32_t u = fu(x);
    return (u + 0x7FFFu + ((u >> 16) & 1u)) & 0xFFFF0000u;
}
__device__ __forceinline__ void sp2b(float a, float b, uint32_t& h, uint32_t& l) {
    uint32_t ra = bfr(a), rb = bfr(b);
    h = (ra >> 16) | (rb & 0xFFFF0000u);
    float la = a - __uint_as_float(ra), lb = b - __uint_as_float(rb);
    uint32_t rla = bfr(la), rlb = bfr(lb);
    l = (rla >> 16) | (rlb & 0xFFFF0000u);
}

// tf32 m16n8k8 (VERIFIED) — projections
__device__ __forceinline__ void mm8(float* c, const uint32_t* a, uint32_t b0, uint32_t b1) {
    asm volatile("mma.sync.aligned.m16n8k8.row.col.f32.tf32.tf32.f32 "
        "{%0,%1,%2,%3},{%4,%5,%6,%7},{%8,%9},{%0,%1,%2,%3};"
        : "+f"(c[0]), "+f"(c[1]), "+f"(c[2]), "+f"(c[3])
        : "r"(a[0]), "r"(a[1]), "r"(a[2]), "r"(a[3]), "r"(b0), "r"(b1));
}
// bf16 m16n8k16 (VERIFIED) — attention
__device__ __forceinline__ void mm16(float* c, const uint32_t* a, uint32_t b0, uint32_t b1) {
    asm volatile("mma.sync.aligned.m16n8k16.row.col.f32.bf16.bf16.f32 "
        "{%0,%1,%2,%3},{%4,%5,%6,%7},{%8,%9},{%0,%1,%2,%3};"
        : "+f"(c[0]), "+f"(c[1]), "+f"(c[2]), "+f"(c[3])
        : "r"(a[0]), "r"(a[1]), "r"(a[2]), "r"(a[3]), "r"(b0), "r"(b1));
}
__device__ __forceinline__ void cpa16(uint32_t saddr, const void* g) {
    asm volatile("cp.async.cg.shared.global [%0],[%1],16;" :: "r"(saddr), "l"(g));
}
#define CPC()  asm volatile("cp.async.commit_group;" ::: "memory")
#define CPW1() asm volatile("cp.async.wait_group 1;" ::: "memory")
#define CPW0() asm volatile("cp.async.wait_group 0;" ::: "memory")

// ============== tf32 MMA projection GEMM (VERIFIED R9-R13, unchanged) ==============
#define PLDA 36

__device__ __forceinline__ void proj_body(const float* __restrict__ A,
                                          const float* __restrict__ W,
                                          float* __restrict__ C) {
    __shared__ float sA[128 * PLDA];
    __shared__ float sW[64 * PLDA];
    const int t = threadIdx.x, w = t >> 5, lane = t & 31;
    const int g = lane >> 2, q4 = lane & 3;
    const int m0 = blockIdx.y * 128, n0 = blockIdx.x * 64;
    const int wm = (w & 3) * 32, wn = (w >> 2) * 32;

    float acc[2][4][4];
    #pragma unroll
    for (int a = 0; a < 2; a++)
        #pragma unroll
        for (int b = 0; b < 4; b++)
            #pragma unroll
            for (int c = 0; c < 4; c++) acc[a][b][c] = 0.f;

    for (int k0 = 0; k0 < DM; k0 += 32) {
        #pragma unroll
        for (int i = 0; i < 4; i++) {
            int e = t + i * 256, r = e >> 3, j = e & 7;
            float4 v = *(const float4*)&A[(size_t)(m0 + r) * DM + k0 + j * 4];
            float* d = &sA[r * PLDA + j * 4];
            d[0] = t32f(v.x); d[1] = t32f(v.y); d[2] = t32f(v.z); d[3] = t32f(v.w);
        }
        #pragma unroll
        for (int i = 0; i < 2; i++) {
            int e = t + i * 256, r = e >> 3, j = e & 7;
            float4 v = *(const float4*)&W[(size_t)(n0 + r) * DM + k0 + j * 4];
            float* d = &sW[r * PLDA + j * 4];
            d[0] = t32f(v.x); d[1] = t32f(v.y); d[2] = t32f(v.z); d[3] = t32f(v.w);
        }
        __syncthreads();
        #pragma unroll
        for (int kk = 0; kk < 32; kk += 8) {
            uint32_t af[2][4];
            #pragma unroll
            for (int mt = 0; mt < 2; mt++) {
                int base = (wm + mt * 16 + g) * PLDA + kk + q4;
                af[mt][0] = fu(sA[base]);
                af[mt][1] = fu(sA[base + 8 * PLDA]);
                af[mt][2] = fu(sA[base + 4]);
                af[mt][3] = fu(sA[base + 8 * PLDA + 4]);
            }
            #pragma unroll
            for (int nt = 0; nt < 4; nt++) {
                int bb = (wn + nt * 8 + g) * PLDA + kk + q4;
                uint32_t b0 = fu(sW[bb]), b1 = fu(sW[bb + 4]);
                mm8(acc[0][nt], af[0], b0, b1);
                mm8(acc[1][nt], af[1], b0, b1);
            }
        }
        __syncthreads();
    }
    #pragma unroll
    for (int mt = 0; mt < 2; mt++)
        #pragma unroll
        for (int nt = 0; nt < 4; nt++) {
            int r0 = m0 + wm + mt * 16 + g;
            int col = n0 + wn + nt * 8 + 2 * q4;
            float* a = acc[mt][nt];
            C[(size_t)r0 * DM + col]           = a[0];
            C[(size_t)r0 * DM + col + 1]       = a[1];
            C[(size_t)(r0 + 8) * DM + col]     = a[2];
            C[(size_t)(r0 + 8) * DM + col + 1] = a[3];
        }
}

__global__ void __launch_bounds__(256, 1)
qkv_proj(const float* __restrict__ x, const float* __restrict__ Wq,
         const float* __restrict__ Wk, const float* __restrict__ Wv) {
    if (blockIdx.z == 0)      proj_body(x, Wq, g_q);
    else if (blockIdx.z == 1) proj_body(x, Wk, g_k);
    else                      proj_body(x, Wv, g_v);
}

__global__ void __launch_bounds__(256, 1)
out_proj(const float* __restrict__ Wo, float* __restrict__ out) {
    proj_body(g_ctx, Wo, out);
}

// ---- Q -> fragment-major A-operand words: word idx = tid*4 + {a0,a1,a2,a3} ----
__global__ void __launch_bounds__(256, 1) splitQ() {
    const float scale = 0.04419417382415922f;  // 1/sqrt(512)
    int tid = blockIdx.x * 256 + threadIdx.x;   // 1M threads
    int lane = tid & 31, kcg = (tid >> 5) & 31, r16 = tid >> 10;
    int g = lane >> 2, q4 = lane & 3;
    const float* P0 = g_q + ((size_t)r16 * 16 + g) * DM + kcg * 16 + 2 * q4;
    float2 x0 = *(const float2*)P0;
    float2 x2 = *(const float2*)(P0 + 8);
    float2 x1 = *(const float2*)(P0 + 8 * DM);
    float2 x3 = *(const float2*)(P0 + 8 * DM + 8);
    uint4 H, L;
    sp2b(x0.x * scale, x0.y * scale, H.x, L.x);
    sp2b(x1.x * scale, x1.y * scale, H.y, L.y);
    sp2b(x2.x * scale, x2.y * scale, H.z, L.z);
    sp2b(x3.x * scale, x3.y * scale, H.w, L.w);
    ((uint4*)g_qh)[tid] = H;
    ((uint4*)g_ql)[tid] = L;
}

// ---- K -> fragment-major B-operand words: word idx = tid*2 + {b0,b1} ----
__global__ void __launch_bounds__(256, 1) splitK() {
    int tid = blockIdx.x * 256 + threadIdx.x;   // 2M threads
    int lane = tid & 31, kcg = (tid >> 5) & 31, kb = tid >> 10;
    int g = lane >> 2, q4 = lane & 3;
    const float* P0 = g_k + ((size_t)kb * 8 + g) * DM + kcg * 16 + 2 * q4;
    float2 x0 = *(const float2*)P0;
    float2 x1 = *(const float2*)(P0 + 8);
    uint2 H, L;
    sp2b(x0.x, x0.y, H.x, L.x);
    sp2b(x1.x, x1.y, H.y, L.y);
    ((uint2*)g_kh)[tid] = H;
    ((uint2*)g_kl)[tid] = L;
}

// ---- V -> transposed fragment-major B-operand (PV: n=d, k=key) ----
__global__ void __launch_bounds__(256, 1) vtrans() {
    int tid = blockIdx.x * 256 + threadIdx.x;   // 2M threads
    int lane = tid & 31, kc = (tid >> 5) & 255, n8 = (tid >> 13) & 63, b = tid >> 19;
    int g = lane >> 2, q4 = lane & 3;
    const float* B0 = g_v + ((size_t)b * SEQ + kc * 16 + 2 * q4) * DM + n8 * 8 + g;
    float v00 = B0[0];
    float v01 = B0[DM];
    float v10 = B0[8 * DM];
    float v11 = B0[9 * DM];
    uint2 H, L;
    sp2b(v00, v01, H.x, L.x);
    sp2b(v10, v11, H.y, L.y);
    ((uint2*)g_vth)[tid] = H;
    ((uint2*)g_vtl)[tid] = L;
}

// ==== split-bf16 MMA flash attention, fragment-major + cp.async pipeline ====
#define LKW 68           // P row stride in words
#define OQH 0            // Q hi 8192 words
#define OQL 8192
#define OB0H 16384       // K/V chunk buffers: 8192 words each
#define OB0L 24576
#define OB1H 32768
#define OB1L 40960
#define OSP  49152       // fp32 S [32][132]=4224 OVERLAYS P hi/lo (4352)
#define OPH  OSP
#define OPL  (OSP + 2176)
#define OA   53504
#define OL   53536
#define A_WORDS 53568
#define A_BYTES (A_WORDS*4)

// stage one chunk pair (hi+lo): 16 blocks x 512 contiguous words, block stride blk
__device__ __forceinline__ void issue_chunk(uint32_t sb, uint32_t ohw, uint32_t olw,
                                            const uint32_t* GH, const uint32_t* GL,
                                            int blk, int t) {
    #pragma unroll
    for (int i = 0; i < 8; i++) {
        int e = t + i * 256;
        int off = (e >> 7) * blk + (e & 127) * 4;
        cpa16(sb + (ohw + e * 4) * 4, GH + off);
        cpa16(sb + (olw + e * 4) * 4, GL + off);
    }
}

__global__ void __launch_bounds__(256, 1) attn() {
    extern __shared__ uint32_t sh[];
    const uint32_t sb = (uint32_t)__cvta_generic_to_shared(sh);
    float* sS = (float*)(sh + OSP);
    float* sAlp = (float*)(sh + OA);
    float* sL = (float*)(sh + OL);
    const int t = threadIdx.x, w = t >> 5, lane = t & 31;
    const int g = lane >> 2, q4 = lane & 3;
    const int qt = 127 - blockIdx.x, b = blockIdx.y;   // longest-first
    const int q0 = qt * 32;
    const int mq = (w & 1) * 16;
    const int wn = (w >> 1) * 32;
    const int row = t >> 3, sub = t & 7;
    const int ktmax = (q0 + 31) >> 7;

    // stage full Q tile (fragment-major). FIX: 16-row block = 1024 uint4 (was 512).
    {
        const uint4* Qh4 = (const uint4*)g_qh + (size_t)(b * SEQ + q0) * 64;
        const uint4* Ql4 = (const uint4*)g_ql + (size_t)(b * SEQ + q0) * 64;
        #pragma unroll
        for (int i = 0; i < 8; i++) {
            int e = t + i * 256;
            *(uint4*)(sh + OQH + e * 4) = Qh4[e];
            *(uint4*)(sh + OQL + e * 4) = Ql4[e];
        }
    }
    // prefetch K chunk 0 of first k-tile into buf0
    issue_chunk(sb, OB0H, OB0L,
                g_kh + ((size_t)(b * SEQ) >> 3) * 2048,
                g_kl + ((size_t)(b * SEQ) >> 3) * 2048, 2048, t);
    CPC();

    float oacc[4][4][4];
    #pragma unroll
    for (int c = 0; c < 4; c++)
        #pragma unroll
        for (int nt = 0; nt < 4; nt++)
            #pragma unroll
            for (int i = 0; i < 4; i++) oacc[c][nt][i] = 0.f;
    float m_run = -INFINITY, l_run = 0.f;

    for (int kt = 0; kt <= ktmax; kt++) {
        const int k0 = kt * 128;
        const uint32_t* KHb = g_kh + ((size_t)(b * SEQ + k0) >> 3) * 2048;
        const uint32_t* KLb = g_kl + ((size_t)(b * SEQ + k0) >> 3) * 2048;
        const uint32_t* VHb = g_vth + (size_t)b * 1048576 + ((size_t)k0 >> 4) * 64;
        const uint32_t* VLb = g_vtl + (size_t)b * 1048576 + ((size_t)k0 >> 4) * 64;
        float sacc[4][4];
        #pragma unroll
        for (int nt = 0; nt < 4; nt++)
            #pragma unroll
            for (int i = 0; i < 4; i++) sacc[nt][i] = 0.f;

        // ---- QK over 4 d-chunks, pipelined ----
        #pragma unroll
        for (int c = 0; c < 4; c++) {
            if (c < 3) {
                uint32_t oh = ((c + 1) & 1) ? OB1H : OB0H;
                uint32_t ol = ((c + 1) & 1) ? OB1L : OB0L;
                issue_chunk(sb, oh, ol, KHb + (c + 1) * 512, KLb + (c + 1) * 512, 2048, t);
            } else {  // prefetch V chunk 0
                issue_chunk(sb, OB0H, OB0L, VHb, VLb, 16384, t);
            }
            CPC();
            CPW1();
            __syncthreads();
            uint32_t okh = (c & 1) ? OB1H : OB0H;
            uint32_t okl = (c & 1) ? OB1L : OB0L;
            #pragma unroll
            for (int kc = 0; kc < 8; kc++) {
                int qw = ((w & 1) * 32 + c * 8 + kc) * 128 + lane * 4;
                uint4 qh = *(uint4*)(sh + OQH + qw);
                uint4 ql = *(uint4*)(sh + OQL + qw);
                uint32_t ah[4] = { qh.x, qh.y, qh.z, qh.w };
                uint32_t al[4] = { ql.x, ql.y, ql.z, ql.w };
                #pragma unroll
                for (int nt = 0; nt < 4; nt++) {
                    int kwd = ((w >> 1) * 4 + nt) * 512 + kc * 64 + lane * 2;
                    uint2 bh = *(uint2*)(sh + okh + kwd);
                    uint2 bl = *(uint2*)(sh + okl + kwd);
                    mm16(sacc[nt], ah, bh.x, bh.y);
                    mm16(sacc[nt], ah, bl.x, bl.y);
                    mm16(sacc[nt], al, bh.x, bh.y);
                }
            }
            __syncthreads();
        }
        // ---- S -> smem (overlay region) ----
        #pragma unroll
        for (int nt = 0; nt < 4; nt++) {
            int r0 = mq + g, col = wn + nt * 8 + 2 * q4;
            sS[r0 * 132 + col]           = sacc[nt][0];
            sS[r0 * 132 + col + 1]       = sacc[nt][1];
            sS[(r0 + 8) * 132 + col]     = sacc[nt][2];
            sS[(r0 + 8) * 132 + col + 1] = sacc[nt][3];
        }
        __syncthreads();
        // ---- online softmax: 8 threads/row, 16 keys each ----
        float sv[16], mx = -INFINITY;
        const bool lastt = (kt == ktmax);
        #pragma unroll
        for (int i = 0; i < 16; i++) {
            float s = sS[row * 132 + sub * 16 + i];
            if (lastt && (k0 + sub * 16 + i > q0 + row)) s = -INFINITY;
            sv[i] = s;
            mx = fmaxf(mx, s);
        }
        #pragma unroll
        for (int o = 1; o < 8; o <<= 1) mx = fmaxf(mx, __shfl_xor_sync(~0u, mx, o));
        float mnew = fmaxf(m_run, mx);
        float alpha = __expf(m_run - mnew);
        float ps = 0.f;
        #pragma unroll
        for (int i = 0; i < 16; i++) { sv[i] = __expf(sv[i] - mnew); ps += sv[i]; }
        #pragma unroll
        for (int o = 1; o < 8; o <<= 1) ps += __shfl_xor_sync(~0u, ps, o);
        l_run = l_run * alpha + ps;
        m_run = mnew;
        __syncthreads();          // all S reads done before P overlays it
        if (sub == 0) sAlp[row] = alpha;
        #pragma unroll
        for (int i = 0; i < 16; i += 2) {
            uint32_t h, l;
            sp2b(sv[i], sv[i + 1], h, l);
            sh[OPH + row * LKW + sub * 8 + (i >> 1)] = h;
            sh[OPL + row * LKW + sub * 8 + (i >> 1)] = l;
        }
        __syncthreads();
        // ---- rescale O ----
        {
            float a0 = sAlp[mq + g], a1 = sAlp[mq + g + 8];
            #pragma unroll
            for (int c = 0; c < 4; c++)
                #pragma unroll
                for (int nt = 0; nt < 4; nt++) {
                    oacc[c][nt][0] *= a0; oacc[c][nt][1] *= a0;
                    oacc[c][nt][2] *= a1; oacc[c][nt][3] *= a1;
                }
        }
        // ---- PV over 4 d-chunks, pipelined (V0 already in flight) ----
        #pragma unroll
        for (int c = 0; c < 4; c++) {
            if (c < 3) {
                uint32_t oh = ((c + 1) & 1) ? OB1H : OB0H;
                uint32_t ol = ((c + 1) & 1) ? OB1L : OB0L;
                issue_chunk(sb, oh, ol, VHb + (size_t)(c + 1) * 16 * 16384,
                            VLb + (size_t)(c + 1) * 16 * 16384, 16384, t);
            } else {  // prefetch next k-tile's K chunk 0
                const int nk0 = (kt < ktmax) ? k0 + 128 : k0;
                issue_chunk(sb, OB0H, OB0L,
                            g_kh + ((size_t)(b * SEQ + nk0) >> 3) * 2048,
                            g_kl + ((size_t)(b * SEQ + nk0) >> 3) * 2048, 2048, t);
            }
            CPC();
            CPW1();
            __syncthreads();
            uint32_t ovh = (c & 1) ? OB1H : OB0H;
            uint32_t ovl = (c & 1) ? OB1L : OB0L;
            #pragma unroll
            for (int kc = 0; kc < 8; kc++) {
                int ab = (mq + g) * LKW + kc * 8 + q4;
                uint32_t ph[4] = { sh[OPH + ab], sh[OPH + ab + 8 * LKW],
                                   sh[OPH + ab + 4], sh[OPH + ab + 8 * LKW + 4] };
                uint32_t pl[4] = { sh[OPL + ab], sh[OPL + ab + 8 * LKW],
                                   sh[OPL + ab + 4], sh[OPL + ab + 8 * LKW + 4] };
                #pragma unroll
                for (int nt = 0; nt < 4; nt++) {
                    int vwd = ((w >> 1) * 4 + nt) * 512 + kc * 64 + lane * 2;
                    uint2 vh = *(uint2*)(sh + ovh + vwd);
                    uint2 vl = *(uint2*)(sh + ovl + vwd);
                    mm16(oacc[c][nt], ph, vh.x, vh.y);
                    mm16(oacc[c][nt], ph, vl.x, vl.y);
                    mm16(oacc[c][nt], pl, vh.x, vh.y);
                }
            }
            __syncthreads();
        }
    }
    // ---- epilogue ----
    CPW0();
    if (sub == 0) sL[row] = l_run;
    __syncthreads();
    {
        float li0 = 1.f / sL[mq + g], li1 = 1.f / sL[mq + g + 8];
        #pragma unroll
        for (int c = 0; c < 4; c++)
            #pragma unroll
            for (int nt = 0; nt < 4; nt++) {
                int col = c * 128 + wn + nt * 8 + 2 * q4;
                size_t r0 = ((size_t)b * SEQ + q0 + mq + g) * DM;
                float* a = oacc[c][nt];
                g_ctx[r0 + col]              = a[0] * li0;
                g_ctx[r0 + col + 1]          = a[1] * li0;
                g_ctx[r0 + 8 * DM + col]     = a[2] * li1;
                g_ctx[r0 + 8 * DM + col + 1] = a[3] * li1;
            }
    }
}

extern "C" void kernel_launch(void* const* d_in, const int* in_sizes, int n_in,
                              void* d_out, int out_size) {
    (void)in_sizes; (void)n_in; (void)out_size;
    const float* x  = (const float*)d_in[0];
    const float* Wq = (const float*)d_in[1];
    const float* Wk = (const float*)d_in[2];
    const float* Wv = (const float*)d_in[3];
    const float* Wo = (const float*)d_in[4];
    float* out = (float*)d_out;

    qkv_proj<<<dim3(8, 128, 3), 256>>>(x, Wq, Wk, Wv);
    splitQ<<<MROWS * DM / 8 / 256, 256>>>();          // 1M threads
    splitK<<<MROWS * DM / 4 / 256, 256>>>();          // 2M threads
    vtrans<<<MROWS * DM / 4 / 256, 256>>>();          // 2M threads

    cudaFuncSetAttribute(attn, cudaFuncAttributeMaxDynamicSharedMemorySize, A_BYTES);
    attn<<<dim3(128, BATCH), 256, A_BYTES>>>();

    out_proj<<<dim3(8, 128), 256>>>(Wo, out);
}

// round 16
// speedup vs baseline: 2.5101x; 1.4466x over previous
#include <cuda_runtime.h>
#include <cuda_fp16.h>
#include <math.h>
#include <stdint.h>

#define BATCH 4
#define SEQ   4096
#define DM    512
#define MROWS (BATCH*SEQ)

__device__ float g_q[MROWS*DM];
__device__ float g_k[MROWS*DM];
__device__ float g_v[MROWS*DM];
__device__ float g_ctx[MROWS*DM];
// fragment-major packed fp16 operands (uint32 words = fp16 pairs)
__device__ __align__(16) uint32_t g_qf[MROWS*DM/2];
__device__ __align__(16) uint32_t g_kf[MROWS*DM/2];
__device__ __align__(16) uint32_t g_vtf[MROWS*DM/2];

__device__ __forceinline__ uint32_t fu(float x) { return __float_as_uint(x); }
// tf32 round (integer ops only — cvt.rna.tf32 is broken on this target)
__device__ __forceinline__ float t32f(float x) {
    uint32_t u = fu(x);
    u = (u + 0x1000u + ((u >> 13) & 1u)) & 0xFFFFE000u;
    return __uint_as_float(u);
}
// pack two floats -> fp16x2 word
__device__ __forceinline__ uint32_t pkh(float a, float b) {
    __half2 h = __floats2half2_rn(a, b);
    return *(uint32_t*)&h;
}

// tf32 m16n8k8 (VERIFIED) — projections
__device__ __forceinline__ void mm8(float* c, const uint32_t* a, uint32_t b0, uint32_t b1) {
    asm volatile("mma.sync.aligned.m16n8k8.row.col.f32.tf32.tf32.f32 "
        "{%0,%1,%2,%3},{%4,%5,%6,%7},{%8,%9},{%0,%1,%2,%3};"
        : "+f"(c[0]), "+f"(c[1]), "+f"(c[2]), "+f"(c[3])
        : "r"(a[0]), "r"(a[1]), "r"(a[2]), "r"(a[3]), "r"(b0), "r"(b1));
}
// fp16 m16n8k16 — attention (single pass)
__device__ __forceinline__ void mm16(float* c, const uint32_t* a, uint32_t b0, uint32_t b1) {
    asm volatile("mma.sync.aligned.m16n8k16.row.col.f32.f16.f16.f32 "
        "{%0,%1,%2,%3},{%4,%5,%6,%7},{%8,%9},{%0,%1,%2,%3};"
        : "+f"(c[0]), "+f"(c[1]), "+f"(c[2]), "+f"(c[3])
        : "r"(a[0]), "r"(a[1]), "r"(a[2]), "r"(a[3]), "r"(b0), "r"(b1));
}
__device__ __forceinline__ void cpa16(uint32_t saddr, const void* g) {
    asm volatile("cp.async.cg.shared.global [%0],[%1],16;" :: "r"(saddr), "l"(g));
}
#define CPC()  asm volatile("cp.async.commit_group;" ::: "memory")
#define CPW1() asm volatile("cp.async.wait_group 1;" ::: "memory")
#define CPW0() asm volatile("cp.async.wait_group 0;" ::: "memory")

// ============== tf32 MMA projection GEMM (VERIFIED R9-R15, unchanged) ==============
#define PLDA 36

__device__ __forceinline__ void proj_body(const float* __restrict__ A,
                                          const float* __restrict__ W,
                                          float* __restrict__ C) {
    __shared__ float sA[128 * PLDA];
    __shared__ float sW[64 * PLDA];
    const int t = threadIdx.x, w = t >> 5, lane = t & 31;
    const int g = lane >> 2, q4 = lane & 3;
    const int m0 = blockIdx.y * 128, n0 = blockIdx.x * 64;
    const int wm = (w & 3) * 32, wn = (w >> 2) * 32;

    float acc[2][4][4];
    #pragma unroll
    for (int a = 0; a < 2; a++)
        #pragma unroll
        for (int b = 0; b < 4; b++)
            #pragma unroll
            for (int c = 0; c < 4; c++) acc[a][b][c] = 0.f;

    for (int k0 = 0; k0 < DM; k0 += 32) {
        #pragma unroll
        for (int i = 0; i < 4; i++) {
            int e = t + i * 256, r = e >> 3, j = e & 7;
            float4 v = *(const float4*)&A[(size_t)(m0 + r) * DM + k0 + j * 4];
            float* d = &sA[r * PLDA + j * 4];
            d[0] = t32f(v.x); d[1] = t32f(v.y); d[2] = t32f(v.z); d[3] = t32f(v.w);
        }
        #pragma unroll
        for (int i = 0; i < 2; i++) {
            int e = t + i * 256, r = e >> 3, j = e & 7;
            float4 v = *(const float4*)&W[(size_t)(n0 + r) * DM + k0 + j * 4];
            float* d = &sW[r * PLDA + j * 4];
            d[0] = t32f(v.x); d[1] = t32f(v.y); d[2] = t32f(v.z); d[3] = t32f(v.w);
        }
        __syncthreads();
        #pragma unroll
        for (int kk = 0; kk < 32; kk += 8) {
            uint32_t af[2][4];
            #pragma unroll
            for (int mt = 0; mt < 2; mt++) {
                int base = (wm + mt * 16 + g) * PLDA + kk + q4;
                af[mt][0] = fu(sA[base]);
                af[mt][1] = fu(sA[base + 8 * PLDA]);
                af[mt][2] = fu(sA[base + 4]);
                af[mt][3] = fu(sA[base + 8 * PLDA + 4]);
            }
            #pragma unroll
            for (int nt = 0; nt < 4; nt++) {
                int bb = (wn + nt * 8 + g) * PLDA + kk + q4;
                uint32_t b0 = fu(sW[bb]), b1 = fu(sW[bb + 4]);
                mm8(acc[0][nt], af[0], b0, b1);
                mm8(acc[1][nt], af[1], b0, b1);
            }
        }
        __syncthreads();
    }
    #pragma unroll
    for (int mt = 0; mt < 2; mt++)
        #pragma unroll
        for (int nt = 0; nt < 4; nt++) {
            int r0 = m0 + wm + mt * 16 + g;
            int col = n0 + wn + nt * 8 + 2 * q4;
            float* a = acc[mt][nt];
            C[(size_t)r0 * DM + col]           = a[0];
            C[(size_t)r0 * DM + col + 1]       = a[1];
            C[(size_t)(r0 + 8) * DM + col]     = a[2];
            C[(size_t)(r0 + 8) * DM + col + 1] = a[3];
        }
}

__global__ void __launch_bounds__(256, 1)
qkv_proj(const float* __restrict__ x, const float* __restrict__ Wq,
         const float* __restrict__ Wk, const float* __restrict__ Wv) {
    if (blockIdx.z == 0)      proj_body(x, Wq, g_q);
    else if (blockIdx.z == 1) proj_body(x, Wk, g_k);
    else                      proj_body(x, Wv, g_v);
}

__global__ void __launch_bounds__(256, 1)
out_proj(const float* __restrict__ Wo, float* __restrict__ out) {
    proj_body(g_ctx, Wo, out);
}

// ---- Q -> fragment-major fp16 A-operand words (scaled by 1/sqrt(512)) ----
__global__ void __launch_bounds__(256, 1) splitQ() {
    const float scale = 0.04419417382415922f;
    int tid = blockIdx.x * 256 + threadIdx.x;   // 1M threads
    int lane = tid & 31, kcg = (tid >> 5) & 31, r16 = tid >> 10;
    int g = lane >> 2, q4 = lane & 3;
    const float* P0 = g_q + ((size_t)r16 * 16 + g) * DM + kcg * 16 + 2 * q4;
    float2 x0 = *(const float2*)P0;
    float2 x2 = *(const float2*)(P0 + 8);
    float2 x1 = *(const float2*)(P0 + 8 * DM);
    float2 x3 = *(const float2*)(P0 + 8 * DM + 8);
    uint4 H;
    H.x = pkh(x0.x * scale, x0.y * scale);
    H.y = pkh(x1.x * scale, x1.y * scale);
    H.z = pkh(x2.x * scale, x2.y * scale);
    H.w = pkh(x3.x * scale, x3.y * scale);
    ((uint4*)g_qf)[tid] = H;
}

// ---- K -> fragment-major fp16 B-operand words ----
__global__ void __launch_bounds__(256, 1) splitK() {
    int tid = blockIdx.x * 256 + threadIdx.x;   // 2M threads
    int lane = tid & 31, kcg = (tid >> 5) & 31, kb = tid >> 10;
    int g = lane >> 2, q4 = lane & 3;
    const float* P0 = g_k + ((size_t)kb * 8 + g) * DM + kcg * 16 + 2 * q4;
    float2 x0 = *(const float2*)P0;
    float2 x1 = *(const float2*)(P0 + 8);
    uint2 H;
    H.x = pkh(x0.x, x0.y);
    H.y = pkh(x1.x, x1.y);
    ((uint2*)g_kf)[tid] = H;
}

// ---- V -> transposed fragment-major fp16 B-operand (PV: n=d, k=key) ----
__global__ void __launch_bounds__(256, 1) vtrans() {
    int tid = blockIdx.x * 256 + threadIdx.x;   // 2M threads
    int lane = tid & 31, kc = (tid >> 5) & 255, n8 = (tid >> 13) & 63, b = tid >> 19;
    int g = lane >> 2, q4 = lane & 3;
    const float* B0 = g_v + ((size_t)b * SEQ + kc * 16 + 2 * q4) * DM + n8 * 8 + g;
    uint2 H;
    H.x = pkh(B0[0], B0[DM]);
    H.y = pkh(B0[8 * DM], B0[9 * DM]);
    ((uint2*)g_vtf)[tid] = H;
}

// ==== fp16 single-pass MMA flash attention, fragment-major + cp.async pipeline ====
#define LKW 68           // P row stride in words
#define OQ  0            // Q: 8192 words
#define OB0 8192         // K/V chunk buffers: 8192 words each
#define OB1 16384
#define OS  24576        // fp32 S [32][132] = 4224 words
#define OP  28800        // P fp16: 32*68 = 2176 words
#define OA  30976
#define OL  31008
#define A_WORDS 31040
#define A_BYTES (A_WORDS*4)

// stage one chunk (8192 words): 16 blocks x 512 contiguous words, block stride blk
__device__ __forceinline__ void issue_chunk(uint32_t sb, uint32_t ow,
                                            const uint32_t* G, int blk, int t) {
    #pragma unroll
    for (int i = 0; i < 8; i++) {
        int e = t + i * 256;
        int off = (e >> 7) * blk + (e & 127) * 4;
        cpa16(sb + (ow + e * 4) * 4, G + off);
    }
}

__global__ void __launch_bounds__(256, 1) attn() {
    extern __shared__ uint32_t sh[];
    const uint32_t sb = (uint32_t)__cvta_generic_to_shared(sh);
    float* sS = (float*)(sh + OS);
    float* sAlp = (float*)(sh + OA);
    float* sL = (float*)(sh + OL);
    const int t = threadIdx.x, w = t >> 5, lane = t & 31;
    const int g = lane >> 2, q4 = lane & 3;
    const int qt = 127 - blockIdx.x, b = blockIdx.y;   // longest-first
    const int q0 = qt * 32;
    const int mq = (w & 1) * 16;
    const int wn = (w >> 1) * 32;
    const int row = t >> 3, sub = t & 7;
    const int ktmax = (q0 + 31) >> 7;

    // stage full Q tile (fragment-major fp16, 8192 words)
    {
        const uint4* Qf4 = (const uint4*)g_qf + (size_t)(b * SEQ + q0) * 64;
        #pragma unroll
        for (int i = 0; i < 8; i++) {
            int e = t + i * 256;
            *(uint4*)(sh + OQ + e * 4) = Qf4[e];
        }
    }
    // prefetch K chunk 0 of first k-tile into buf0
    issue_chunk(sb, OB0, g_kf + ((size_t)(b * SEQ) >> 3) * 2048, 2048, t);
    CPC();

    float oacc[4][4][4];
    #pragma unroll
    for (int c = 0; c < 4; c++)
        #pragma unroll
        for (int nt = 0; nt < 4; nt++)
            #pragma unroll
            for (int i = 0; i < 4; i++) oacc[c][nt][i] = 0.f;
    float m_run = -INFINITY, l_run = 0.f;

    for (int kt = 0; kt <= ktmax; kt++) {
        const int k0 = kt * 128;
        const uint32_t* KFb = g_kf + ((size_t)(b * SEQ + k0) >> 3) * 2048;
        const uint32_t* VFb = g_vtf + (size_t)b * 1048576 + ((size_t)k0 >> 4) * 64;
        float sacc[4][4];
        #pragma unroll
        for (int nt = 0; nt < 4; nt++)
            #pragma unroll
            for (int i = 0; i < 4; i++) sacc[nt][i] = 0.f;

        // ---- QK over 4 d-chunks, pipelined ----
        #pragma unroll
        for (int c = 0; c < 4; c++) {
            if (c < 3) {
                issue_chunk(sb, ((c + 1) & 1) ? OB1 : OB0, KFb + (c + 1) * 512, 2048, t);
            } else {  // prefetch V chunk 0
                issue_chunk(sb, OB0, VFb, 16384, t);
            }
            CPC();
            CPW1();
            __syncthreads();
            uint32_t ok = (c & 1) ? OB1 : OB0;
            #pragma unroll
            for (int kc = 0; kc < 8; kc++) {
                int qw = ((w & 1) * 32 + c * 8 + kc) * 128 + lane * 4;
                uint4 qh = *(uint4*)(sh + OQ + qw);
                uint32_t ah[4] = { qh.x, qh.y, qh.z, qh.w };
                #pragma unroll
                for (int nt = 0; nt < 4; nt++) {
                    int kwd = ((w >> 1) * 4 + nt) * 512 + kc * 64 + lane * 2;
                    uint2 bh = *(uint2*)(sh + ok + kwd);
                    mm16(sacc[nt], ah, bh.x, bh.y);
                }
            }
            __syncthreads();
        }
        // ---- S -> smem ----
        #pragma unroll
        for (int nt = 0; nt < 4; nt++) {
            int r0 = mq + g, col = wn + nt * 8 + 2 * q4;
            sS[r0 * 132 + col]           = sacc[nt][0];
            sS[r0 * 132 + col + 1]       = sacc[nt][1];
            sS[(r0 + 8) * 132 + col]     = sacc[nt][2];
            sS[(r0 + 8) * 132 + col + 1] = sacc[nt][3];
        }
        __syncthreads();
        // ---- online softmax: 8 threads/row, 16 keys each ----
        float sv[16], mx = -INFINITY;
        const bool lastt = (kt == ktmax);
        #pragma unroll
        for (int i = 0; i < 16; i++) {
            float s = sS[row * 132 + sub * 16 + i];
            if (lastt && (k0 + sub * 16 + i > q0 + row)) s = -INFINITY;
            sv[i] = s;
            mx = fmaxf(mx, s);
        }
        #pragma unroll
        for (int o = 1; o < 8; o <<= 1) mx = fmaxf(mx, __shfl_xor_sync(~0u, mx, o));
        float mnew = fmaxf(m_run, mx);
        float alpha = __expf(m_run - mnew);
        float ps = 0.f;
        #pragma unroll
        for (int i = 0; i < 16; i++) { sv[i] = __expf(sv[i] - mnew); ps += sv[i]; }
        #pragma unroll
        for (int o = 1; o < 8; o <<= 1) ps += __shfl_xor_sync(~0u, ps, o);
        l_run = l_run * alpha + ps;
        m_run = mnew;
        if (sub == 0) sAlp[row] = alpha;
        #pragma unroll
        for (int i = 0; i < 16; i += 2)
            sh[OP + row * LKW + sub * 8 + (i >> 1)] = pkh(sv[i], sv[i + 1]);
        __syncthreads();
        // ---- rescale O ----
        {
            float a0 = sAlp[mq + g], a1 = sAlp[mq + g + 8];
            #pragma unroll
            for (int c = 0; c < 4; c++)
                #pragma unroll
                for (int nt = 0; nt < 4; nt++) {
                    oacc[c][nt][0] *= a0; oacc[c][nt][1] *= a0;
                    oacc[c][nt][2] *= a1; oacc[c][nt][3] *= a1;
                }
        }
        // ---- PV over 4 d-chunks, pipelined (V0 already in flight) ----
        #pragma unroll
        for (int c = 0; c < 4; c++) {
            if (c < 3) {
                issue_chunk(sb, ((c + 1) & 1) ? OB1 : OB0,
                            VFb + (size_t)(c + 1) * 16 * 16384, 16384, t);
            } else {  // prefetch next k-tile's K chunk 0
                const int nk0 = (kt < ktmax) ? k0 + 128 : k0;
                issue_chunk(sb, OB0, g_kf + ((size_t)(b * SEQ + nk0) >> 3) * 2048, 2048, t);
            }
            CPC();
            CPW1();
            __syncthreads();
            uint32_t ov = (c & 1) ? OB1 : OB0;
            #pragma unroll
            for (int kc = 0; kc < 8; kc++) {
                int ab = (mq + g) * LKW + kc * 8 + q4;
                uint32_t ph[4] = { sh[OP + ab], sh[OP + ab + 8 * LKW],
                                   sh[OP + ab + 4], sh[OP + ab + 8 * LKW + 4] };
                #pragma unroll
                for (int nt = 0; nt < 4; nt++) {
                    int vwd = ((w >> 1) * 4 + nt) * 512 + kc * 64 + lane * 2;
                    uint2 vh = *(uint2*)(sh + ov + vwd);
                    mm16(oacc[c][nt], ph, vh.x, vh.y);
                }
            }
            __syncthreads();
        }
    }
    // ---- epilogue ----
    CPW0();
    if (sub == 0) sL[row] = l_run;
    __syncthreads();
    {
        float li0 = 1.f / sL[mq + g], li1 = 1.f / sL[mq + g + 8];
        #pragma unroll
        for (int c = 0; c < 4; c++)
            #pragma unroll
            for (int nt = 0; nt < 4; nt++) {
                int col = c * 128 + wn + nt * 8 + 2 * q4;
                size_t r0 = ((size_t)b * SEQ + q0 + mq + g) * DM;
                float* a = oacc[c][nt];
                g_ctx[r0 + col]              = a[0] * li0;
                g_ctx[r0 + col + 1]          = a[1] * li0;
                g_ctx[r0 + 8 * DM + col]     = a[2] * li1;
                g_ctx[r0 + 8 * DM + col + 1] = a[3] * li1;
            }
    }
}

extern "C" void kernel_launch(void* const* d_in, const int* in_sizes, int n_in,
                              void* d_out, int out_size) {
    (void)in_sizes; (void)n_in; (void)out_size;
    const float* x  = (const float*)d_in[0];
    const float* Wq = (const float*)d_in[1];
    const float* Wk = (const float*)d_in[2];
    const float* Wv = (const float*)d_in[3];
    const float* Wo = (const float*)d_in[4];
    float* out = (float*)d_out;

    qkv_proj<<<dim3(8, 128, 3), 256>>>(x, Wq, Wk, Wv);
    splitQ<<<MROWS * DM / 8 / 256, 256>>>();
    splitK<<<MROWS * DM / 4 / 256, 256>>>();
    vtrans<<<MROWS * DM / 4 / 256, 256>>>();

    cudaFuncSetAttribute(attn, cudaFuncAttributeMaxDynamicSharedMemorySize, A_BYTES);
    attn<<<dim3(128, BATCH), 256, A_BYTES>>>();

    out_proj<<<dim3(8, 128), 256>>>(Wo, out);
}

// round 17
// speedup vs baseline: 2.9825x; 1.1882x over previous
#include <cuda_runtime.h>
#include <cuda_fp16.h>
#include <math.h>
#include <stdint.h>

#define BATCH 4
#define SEQ   4096
#define DM    512
#define MROWS (BATCH*SEQ)

__device__ float g_v[MROWS*DM];
__device__ float g_ctx[MROWS*DM];
// fragment-major packed fp16 operands (uint32 words = fp16 pairs)
__device__ __align__(16) uint32_t g_qf[MROWS*DM/2];
__device__ __align__(16) uint32_t g_kf[MROWS*DM/2];
__device__ __align__(16) uint32_t g_vtf[MROWS*DM/2];

__device__ __forceinline__ uint32_t pkh(float a, float b) {
    __half2 h = __floats2half2_rn(a, b);
    return *(uint32_t*)&h;
}

// fp16 m16n8k16, fp32 accum (VERIFIED R16)
__device__ __forceinline__ void mm16(float* c, const uint32_t* a, uint32_t b0, uint32_t b1) {
    asm volatile("mma.sync.aligned.m16n8k16.row.col.f32.f16.f16.f32 "
        "{%0,%1,%2,%3},{%4,%5,%6,%7},{%8,%9},{%0,%1,%2,%3};"
        : "+f"(c[0]), "+f"(c[1]), "+f"(c[2]), "+f"(c[3])
        : "r"(a[0]), "r"(a[1]), "r"(a[2]), "r"(a[3]), "r"(b0), "r"(b1));
}
__device__ __forceinline__ void cpa16(uint32_t saddr, const void* g) {
    asm volatile("cp.async.cg.shared.global [%0],[%1],16;" :: "r"(saddr), "l"(g));
}
#define CPC()  asm volatile("cp.async.commit_group;" ::: "memory")
#define CPW1() asm volatile("cp.async.wait_group 1;" ::: "memory")
#define CPW0() asm volatile("cp.async.wait_group 0;" ::: "memory")

// ===== fp16 MMA projection GEMM: C[16384,512] = A @ W^T =====
// tile 128M x 64N, K-chunk 32 (16 kpairs), stride-20 fp16-pair smem (conflict-free).
// mode 0: fp32 out; mode 1: Q fragment-major out (scaled); mode 2: K fragment-major out.
#define PLD16 20

__device__ __forceinline__ void proj_body(const float* __restrict__ A,
                                          const float* __restrict__ W,
                                          float* __restrict__ Cf,
                                          float scale, int mode) {
    __shared__ uint32_t sA16[128 * PLD16];
    __shared__ uint32_t sW16[64 * PLD16];
    const int t = threadIdx.x, w = t >> 5, lane = t & 31;
    const int g = lane >> 2, q4 = lane & 3;
    const int m0 = blockIdx.y * 128, n0 = blockIdx.x * 64;
    const int wm = (w & 3) * 32, wn = (w >> 2) * 32;

    float acc[2][4][4];
    #pragma unroll
    for (int a = 0; a < 2; a++)
        #pragma unroll
        for (int b = 0; b < 4; b++)
            #pragma unroll
            for (int c = 0; c < 4; c++) acc[a][b][c] = 0.f;

    for (int k0 = 0; k0 < DM; k0 += 32) {
        #pragma unroll
        for (int i = 0; i < 8; i++) {          // A: 128 rows x 16 kpairs
            int e = t + i * 256, r = e >> 4, j = e & 15;
            float2 v = *(const float2*)&A[(size_t)(m0 + r) * DM + k0 + j * 2];
            sA16[r * PLD16 + j] = pkh(v.x, v.y);
        }
        #pragma unroll
        for (int i = 0; i < 4; i++) {          // W: 64 rows x 16 kpairs
            int e = t + i * 256, r = e >> 4, j = e & 15;
            float2 v = *(const float2*)&W[(size_t)(n0 + r) * DM + k0 + j * 2];
            sW16[r * PLD16 + j] = pkh(v.x, v.y);
        }
        __syncthreads();
        #pragma unroll
        for (int kk = 0; kk < 2; kk++) {       // two k16 steps
            uint32_t af[2][4];
            #pragma unroll
            for (int mt = 0; mt < 2; mt++) {
                int base = (wm + mt * 16 + g) * PLD16 + kk * 8 + q4;
                af[mt][0] = sA16[base];
                af[mt][1] = sA16[base + 8 * PLD16];
                af[mt][2] = sA16[base + 4];
                af[mt][3] = sA16[base + 8 * PLD16 + 4];
            }
            #pragma unroll
            for (int nt = 0; nt < 4; nt++) {
                int bb = (wn + nt * 8 + g) * PLD16 + kk * 8 + q4;
                uint32_t b0 = sW16[bb], b1 = sW16[bb + 4];
                mm16(acc[0][nt], af[0], b0, b1);
                mm16(acc[1][nt], af[1], b0, b1);
            }
        }
        __syncthreads();
    }
    #pragma unroll
    for (int mt = 0; mt < 2; mt++)
        #pragma unroll
        for (int nt = 0; nt < 4; nt++) {
            int gr  = m0 + wm + mt * 16;             // 16-row group base
            int col = n0 + wn + nt * 8 + 2 * q4;
            float* a = acc[mt][nt];
            if (mode == 0) {
                Cf[(size_t)(gr + g) * DM + col]           = a[0];
                Cf[(size_t)(gr + g) * DM + col + 1]       = a[1];
                Cf[(size_t)(gr + g + 8) * DM + col]       = a[2];
                Cf[(size_t)(gr + g + 8) * DM + col + 1]   = a[3];
            } else if (mode == 1) {
                // Q fragment-major (matches R16 splitQ layout), scaled
                int kcg = col >> 4, wsel = ((col & 15) >= 8) ? 2 : 0;
                size_t tq = (size_t)(gr >> 4) * 1024 + kcg * 32 + lane;
                g_qf[tq * 4 + wsel]     = pkh(a[0] * scale, a[1] * scale);
                g_qf[tq * 4 + wsel + 1] = pkh(a[2] * scale, a[3] * scale);
            } else {
                // K fragment-major (matches R16 splitK layout)
                int kcg = col >> 4, wsel = ((col & 15) >= 8) ? 1 : 0;
                size_t kb = (size_t)(gr >> 3);
                g_kf[(kb * 1024 + kcg * 32 + lane) * 2 + wsel]       = pkh(a[0], a[1]);
                g_kf[((kb + 1) * 1024 + kcg * 32 + lane) * 2 + wsel] = pkh(a[2], a[3]);
            }
        }
}

__global__ void __launch_bounds__(256, 1)
qkv_proj(const float* __restrict__ x, const float* __restrict__ Wq,
         const float* __restrict__ Wk, const float* __restrict__ Wv) {
    const float qscale = 0.04419417382415922f;  // 1/sqrt(512)
    if (blockIdx.z == 0)      proj_body(x, Wq, nullptr, qscale, 1);
    else if (blockIdx.z == 1) proj_body(x, Wk, nullptr, 1.f, 2);
    else                      proj_body(x, Wv, g_v, 1.f, 0);
}

__global__ void __launch_bounds__(256, 1)
out_proj(const float* __restrict__ Wo, float* __restrict__ out) {
    proj_body(g_ctx, Wo, out, 1.f, 0);
}

// ---- V -> transposed fragment-major fp16 B-operand (PV: n=d, k=key) ----
__global__ void __launch_bounds__(256, 1) vtrans() {
    int tid = blockIdx.x * 256 + threadIdx.x;   // 2M threads
    int lane = tid & 31, kc = (tid >> 5) & 255, n8 = (tid >> 13) & 63, b = tid >> 19;
    int g = lane >> 2, q4 = lane & 3;
    const float* B0 = g_v + ((size_t)b * SEQ + kc * 16 + 2 * q4) * DM + n8 * 8 + g;
    uint2 H;
    H.x = pkh(B0[0], B0[DM]);
    H.y = pkh(B0[8 * DM], B0[9 * DM]);
    ((uint2*)g_vtf)[tid] = H;
}

// ==== fp16 single-pass MMA flash attention (VERIFIED R16, unchanged) ====
#define LKW 68
#define OQ  0
#define OB0 8192
#define OB1 16384
#define OS  24576
#define OP  28800
#define OA  30976
#define OL  31008
#define A_WORDS 31040
#define A_BYTES (A_WORDS*4)

__device__ __forceinline__ void issue_chunk(uint32_t sb, uint32_t ow,
                                            const uint32_t* G, int blk, int t) {
    #pragma unroll
    for (int i = 0; i < 8; i++) {
        int e = t + i * 256;
        int off = (e >> 7) * blk + (e & 127) * 4;
        cpa16(sb + (ow + e * 4) * 4, G + off);
    }
}

__global__ void __launch_bounds__(256, 1) attn() {
    extern __shared__ uint32_t sh[];
    const uint32_t sb = (uint32_t)__cvta_generic_to_shared(sh);
    float* sS = (float*)(sh + OS);
    float* sAlp = (float*)(sh + OA);
    float* sL = (float*)(sh + OL);
    const int t = threadIdx.x, w = t >> 5, lane = t & 31;
    const int g = lane >> 2, q4 = lane & 3;
    const int qt = 127 - blockIdx.x, b = blockIdx.y;   // longest-first
    const int q0 = qt * 32;
    const int mq = (w & 1) * 16;
    const int wn = (w >> 1) * 32;
    const int row = t >> 3, sub = t & 7;
    const int ktmax = (q0 + 31) >> 7;

    // stage full Q tile (fragment-major fp16, 8192 words)
    {
        const uint4* Qf4 = (const uint4*)g_qf + (size_t)(b * SEQ + q0) * 64;
        #pragma unroll
        for (int i = 0; i < 8; i++) {
            int e = t + i * 256;
            *(uint4*)(sh + OQ + e * 4) = Qf4[e];
        }
    }
    issue_chunk(sb, OB0, g_kf + ((size_t)(b * SEQ) >> 3) * 2048, 2048, t);
    CPC();

    float oacc[4][4][4];
    #pragma unroll
    for (int c = 0; c < 4; c++)
        #pragma unroll
        for (int nt = 0; nt < 4; nt++)
            #pragma unroll
            for (int i = 0; i < 4; i++) oacc[c][nt][i] = 0.f;
    float m_run = -INFINITY, l_run = 0.f;

    for (int kt = 0; kt <= ktmax; kt++) {
        const int k0 = kt * 128;
        const uint32_t* KFb = g_kf + ((size_t)(b * SEQ + k0) >> 3) * 2048;
        const uint32_t* VFb = g_vtf + (size_t)b * 1048576 + ((size_t)k0 >> 4) * 64;
        float sacc[4][4];
        #pragma unroll
        for (int nt = 0; nt < 4; nt++)
            #pragma unroll
            for (int i = 0; i < 4; i++) sacc[nt][i] = 0.f;

        // ---- QK over 4 d-chunks, pipelined ----
        #pragma unroll
        for (int c = 0; c < 4; c++) {
            if (c < 3) {
                issue_chunk(sb, ((c + 1) & 1) ? OB1 : OB0, KFb + (c + 1) * 512, 2048, t);
            } else {
                issue_chunk(sb, OB0, VFb, 16384, t);
            }
            CPC();
            CPW1();
            __syncthreads();
            uint32_t ok = (c & 1) ? OB1 : OB0;
            #pragma unroll
            for (int kc = 0; kc < 8; kc++) {
                int qw = ((w & 1) * 32 + c * 8 + kc) * 128 + lane * 4;
                uint4 qh = *(uint4*)(sh + OQ + qw);
                uint32_t ah[4] = { qh.x, qh.y, qh.z, qh.w };
                #pragma unroll
                for (int nt = 0; nt < 4; nt++) {
                    int kwd = ((w >> 1) * 4 + nt) * 512 + kc * 64 + lane * 2;
                    uint2 bh = *(uint2*)(sh + ok + kwd);
                    mm16(sacc[nt], ah, bh.x, bh.y);
                }
            }
            __syncthreads();
        }
        // ---- S -> smem ----
        #pragma unroll
        for (int nt = 0; nt < 4; nt++) {
            int r0 = mq + g, col = wn + nt * 8 + 2 * q4;
            sS[r0 * 132 + col]           = sacc[nt][0];
            sS[r0 * 132 + col + 1]       = sacc[nt][1];
            sS[(r0 + 8) * 132 + col]     = sacc[nt][2];
            sS[(r0 + 8) * 132 + col + 1] = sacc[nt][3];
        }
        __syncthreads();
        // ---- online softmax: 8 threads/row, 16 keys each ----
        float sv[16], mx = -INFINITY;
        const bool lastt = (kt == ktmax);
        #pragma unroll
        for (int i = 0; i < 16; i++) {
            float s = sS[row * 132 + sub * 16 + i];
            if (lastt && (k0 + sub * 16 + i > q0 + row)) s = -INFINITY;
            sv[i] = s;
            mx = fmaxf(mx, s);
        }
        #pragma unroll
        for (int o = 1; o < 8; o <<= 1) mx = fmaxf(mx, __shfl_xor_sync(~0u, mx, o));
        float mnew = fmaxf(m_run, mx);
        float alpha = __expf(m_run - mnew);
        float ps = 0.f;
        #pragma unroll
        for (int i = 0; i < 16; i++) { sv[i] = __expf(sv[i] - mnew); ps += sv[i]; }
        #pragma unroll
        for (int o = 1; o < 8; o <<= 1) ps += __shfl_xor_sync(~0u, ps, o);
        l_run = l_run * alpha + ps;
        m_run = mnew;
        if (sub == 0) sAlp[row] = alpha;
        #pragma unroll
        for (int i = 0; i < 16; i += 2)
            sh[OP + row * LKW + sub * 8 + (i >> 1)] = pkh(sv[i], sv[i + 1]);
        __syncthreads();
        // ---- rescale O ----
        {
            float a0 = sAlp[mq + g], a1 = sAlp[mq + g + 8];
            #pragma unroll
            for (int c = 0; c < 4; c++)
                #pragma unroll
                for (int nt = 0; nt < 4; nt++) {
                    oacc[c][nt][0] *= a0; oacc[c][nt][1] *= a0;
                    oacc[c][nt][2] *= a1; oacc[c][nt][3] *= a1;
                }
        }
        // ---- PV over 4 d-chunks, pipelined (V0 already in flight) ----
        #pragma unroll
        for (int c = 0; c < 4; c++) {
            if (c < 3) {
                issue_chunk(sb, ((c + 1) & 1) ? OB1 : OB0,
                            VFb + (size_t)(c + 1) * 16 * 16384, 16384, t);
            } else {
                const int nk0 = (kt < ktmax) ? k0 + 128 : k0;
                issue_chunk(sb, OB0, g_kf + ((size_t)(b * SEQ + nk0) >> 3) * 2048, 2048, t);
            }
            CPC();
            CPW1();
            __syncthreads();
            uint32_t ov = (c & 1) ? OB1 : OB0;
            #pragma unroll
            for (int kc = 0; kc < 8; kc++) {
                int ab = (mq + g) * LKW + kc * 8 + q4;
                uint32_t ph[4] = { sh[OP + ab], sh[OP + ab + 8 * LKW],
                                   sh[OP + ab + 4], sh[OP + ab + 8 * LKW + 4] };
                #pragma unroll
                for (int nt = 0; nt < 4; nt++) {
                    int vwd = ((w >> 1) * 4 + nt) * 512 + kc * 64 + lane * 2;
                    uint2 vh = *(uint2*)(sh + ov + vwd);
                    mm16(oacc[c][nt], ph, vh.x, vh.y);
                }
            }
            __syncthreads();
        }
    }
    // ---- epilogue ----
    CPW0();
    if (sub == 0) sL[row] = l_run;
    __syncthreads();
    {
        float li0 = 1.f / sL[mq + g], li1 = 1.f / sL[mq + g + 8];
        #pragma unroll
        for (int c = 0; c < 4; c++)
            #pragma unroll
            for (int nt = 0; nt < 4; nt++) {
                int col = c * 128 + wn + nt * 8 + 2 * q4;
                size_t r0 = ((size_t)b * SEQ + q0 + mq + g) * DM;
                float* a = oacc[c][nt];
                g_ctx[r0 + col]              = a[0] * li0;
                g_ctx[r0 + col + 1]          = a[1] * li0;
                g_ctx[r0 + 8 * DM + col]     = a[2] * li1;
                g_ctx[r0 + 8 * DM + col + 1] = a[3] * li1;
            }
    }
}

extern "C" void kernel_launch(void* const* d_in, const int* in_sizes, int n_in,
                              void* d_out, int out_size) {
    (void)in_sizes; (void)n_in; (void)out_size;
    const float* x  = (const float*)d_in[0];
    const float* Wq = (const float*)d_in[1];
    const float* Wk = (const float*)d_in[2];
    const float* Wv = (const float*)d_in[3];
    const float* Wo = (const float*)d_in[4];
    float* out = (float*)d_out;

    qkv_proj<<<dim3(8, 128, 3), 256>>>(x, Wq, Wk, Wv);
    vtrans<<<MROWS * DM / 4 / 256, 256>>>();

    cudaFuncSetAttribute(attn, cudaFuncAttributeMaxDynamicSharedMemorySize, A_BYTES);
    attn<<<dim3(128, BATCH), 256, A_BYTES>>>();

    out_proj<<<dim3(8, 128), 256>>>(Wo, out);
}